// round 9
// baseline (speedup 1.0000x reference)
#include <cuda_runtime.h>
#include <cuda_fp16.h>
#include <math.h>
#include <cstdint>

// Problem constants: B=4, L=2048, D=1024, H=16, Dh=64, 3D=3072
#define BATCH   4
#define SEQ     2048
#define EMBD    1024
#define NHEAD   16
#define HDIM    64
#define TOKENS  (BATCH * SEQ)            // 8192
#define QKVDIM  (3 * EMBD)               // 3072

// ---------------- scratch (static __device__, no allocation) ----------------
__device__ __half g_q[(size_t)BATCH * NHEAD * SEQ * HDIM];  // [B,H,L,Dh] /8, perm16
__device__ __half g_k[(size_t)BATCH * NHEAD * SEQ * HDIM];  // perm16
__device__ __half g_v[(size_t)BATCH * NHEAD * HDIM * SEQ];  // [B,H,Dh,L] (transposed!)
__device__ __half g_att[(size_t)TOKENS * EMBD];             // [B,L,D] perm16
__device__ float2 g_rope[(size_t)SEQ * 32];                 // cos/sin table
__device__ __half g_xh[(size_t)TOKENS * EMBD];              // x fp16, perm16
__device__ __half g_wqkvT[(size_t)QKVDIM * EMBD];           // W_qkv^T fp16, perm16
__device__ __half g_wprojT[(size_t)EMBD * EMBD];            // W_proj^T fp16, perm16

// ---------------- helpers ---------------------------------------------------
__device__ __forceinline__ void mma_f16(float* d, const uint32_t* a,
                                        const uint32_t* b) {
  asm volatile(
      "mma.sync.aligned.m16n8k16.row.col.f32.f16.f16.f32 "
      "{%0,%1,%2,%3},{%4,%5,%6,%7},{%8,%9},{%0,%1,%2,%3};"
      : "+f"(d[0]), "+f"(d[1]), "+f"(d[2]), "+f"(d[3])
      : "r"(a[0]), "r"(a[1]), "r"(a[2]), "r"(a[3]), "r"(b[0]), "r"(b[1]));
}

#define CPA16(dst, src) \
  asm volatile("cp.async.cg.shared.global [%0], [%1], 16;\n" ::"r"(dst), "l"(src))

// 16-group permutation: pair j (0..7) goes to pair position (j&3)*2 + (j>>2).
// Thread tig then finds k={2t,2t+1,2t+8,2t+9} contiguous at offset 4t.
__device__ __host__ __forceinline__ int perm16(int k) {
  const int j = (k & 15) >> 1;
  return (k & ~15) + (((j & 3) * 2 + (j >> 2)) << 1) + (k & 1);
}

// ---------------- RoPE cos/sin table ----------------------------------------
__global__ __launch_bounds__(256) void rope_table_kernel() {
  const int idx = blockIdx.x * 256 + threadIdx.x;  // 0..65535
  const int l = idx >> 5, i = idx & 31;
  const float inv_freq = 1.0f / powf(10000.0f, (2.0f * (float)i) / 64.0f);
  float s, c;
  sincosf((float)l * inv_freq, &s, &c);
  g_rope[idx] = make_float2(c, s);
}

// ------------- fp16 round + 16-group permute (A operands) -------------------
__global__ __launch_bounds__(256) void round_permute_half(
    const float* __restrict__ in, __half* __restrict__ out, int n16) {
  int i = blockIdx.x * 256 + threadIdx.x;  // one 16-float group per thread
  const int stride = gridDim.x * 256;
  for (; i < n16; i += stride) {
    const float4* ip = (const float4*)(in + 16 * (size_t)i);
    float v[16];
    *(float4*)(v + 0) = ip[0];
    *(float4*)(v + 4) = ip[1];
    *(float4*)(v + 8) = ip[2];
    *(float4*)(v + 12) = ip[3];
    __half h[16];
#pragma unroll
    for (int j = 0; j < 8; j++) {
      const int pp = (j & 3) * 2 + (j >> 2);
      h[pp * 2] = __float2half_rn(v[2 * j]);
      h[pp * 2 + 1] = __float2half_rn(v[2 * j + 1]);
    }
    uint4* op = (uint4*)(out + 16 * (size_t)i);
    op[0] = *(uint4*)(h);
    op[1] = *(uint4*)(h + 8);
  }
}

// ------------- transpose + fp16 round + permute (B/weight operands) ---------
// in: [K][N] row-major -> out: [N][K] fp16, k 16-group permuted
__global__ __launch_bounds__(256) void transpose_permute_half(
    const float* __restrict__ in, __half* __restrict__ out, int K, int N) {
  __shared__ float tile[32][33];
  const int k0 = blockIdx.y * 32, n0 = blockIdx.x * 32;
  const int tx = threadIdx.x, ty = threadIdx.y;  // 32 x 8
#pragma unroll
  for (int i = 0; i < 32; i += 8)
    tile[ty + i][tx] = in[(size_t)(k0 + ty + i) * N + n0 + tx];
  __syncthreads();
  const int pk = perm16(tx);
#pragma unroll
  for (int i = 0; i < 32; i += 8) {
    const int n = ty + i;
    out[(size_t)(n0 + n) * K + k0 + pk] = __float2half_rn(tile[tx][n]);
  }
}

// ---------------- GEMM core (fp16 operands, fp32 accum) ---------------------
// A: [M][K] perm16; BT: [N][K] perm16. BK=32. 128x128 tile, 256 threads.
#define ABS_H 48                        // smem row stride in halves (96B)
#define AB_BUF_H (128 * ABS_H)          // 6144 halves
#define GEMM_SMEM (4 * AB_BUF_H * 2)    // 49152 B

__device__ __forceinline__ void gemm_tile_compute(
    const __half* __restrict__ A, const __half* __restrict__ BT, __half* sm,
    int m0, int n0, int K, float acc[4][4][4]) {
  const int tid = threadIdx.x;
  const int warp = tid >> 5, lane = tid & 31;
  const int wm = warp >> 2, wn = warp & 3;
  const int g = lane >> 2, tig = lane & 3;

#pragma unroll
  for (int i = 0; i < 4; i++)
#pragma unroll
    for (int j = 0; j < 4; j++)
#pragma unroll
      for (int t = 0; t < 4; t++) acc[i][j][t] = 0.0f;

  auto prefetch = [&](int kt, int buf) {
    __half* As = sm + buf * AB_BUF_H;
    __half* Bs = sm + 2 * AB_BUF_H + buf * AB_BUF_H;
    const int k0 = kt << 5;
#pragma unroll
    for (int j = 0; j < 2; j++) {
      const int p = tid + (j << 8);
      const int r = p >> 2, c = (p & 3) << 3;  // 128 rows x 4 16B-chunks
      uint32_t da = (uint32_t)__cvta_generic_to_shared(As + r * ABS_H + c);
      CPA16(da, A + (size_t)(m0 + r) * K + k0 + c);
      uint32_t db = (uint32_t)__cvta_generic_to_shared(Bs + r * ABS_H + c);
      CPA16(db, BT + (size_t)(n0 + r) * K + k0 + c);
    }
    asm volatile("cp.async.commit_group;\n");
  };

  const int NT = K >> 5;
  prefetch(0, 0);

  for (int kt = 0; kt < NT; kt++) {
    const int buf = kt & 1;
    if (kt + 1 < NT) {
      prefetch(kt + 1, buf ^ 1);
      asm volatile("cp.async.wait_group 1;\n");
    } else {
      asm volatile("cp.async.wait_group 0;\n");
    }
    __syncthreads();

    const __half* As = sm + buf * AB_BUF_H;
    const __half* Bs = sm + 2 * AB_BUF_H + buf * AB_BUF_H;

#pragma unroll
    for (int ks = 0; ks < 2; ks++) {
      const int koff = ks * 16 + 4 * tig;
      uint32_t af[4][4], bf[4][2];
#pragma unroll
      for (int mt = 0; mt < 4; mt++) {
        const int row = wm * 64 + mt * 16 + g;
        uint2 a02 = *(const uint2*)(As + row * ABS_H + koff);
        uint2 a13 = *(const uint2*)(As + (row + 8) * ABS_H + koff);
        af[mt][0] = a02.x;
        af[mt][2] = a02.y;
        af[mt][1] = a13.x;
        af[mt][3] = a13.y;
      }
#pragma unroll
      for (int nt = 0; nt < 4; nt++) {
        const int nrow = wn * 32 + nt * 8 + g;
        uint2 b01 = *(const uint2*)(Bs + nrow * ABS_H + koff);
        bf[nt][0] = b01.x;
        bf[nt][1] = b01.y;
      }
#pragma unroll
      for (int mt = 0; mt < 4; mt++)
#pragma unroll
        for (int nt = 0; nt < 4; nt++) mma_f16(acc[mt][nt], af[mt], bf[nt]);
    }
    __syncthreads();
  }
}

// ---------------- plain GEMM + bias (proj, fp32 out) ------------------------
__global__ __launch_bounds__(256) void gemm_f16_kernel(
    const __half* __restrict__ A, const __half* __restrict__ BT,
    const float* __restrict__ bias, float* __restrict__ C, int N, int K) {
  extern __shared__ __half smh[];
  const int tid = threadIdx.x;
  const int warp = tid >> 5, lane = tid & 31;
  const int wm = warp >> 2, wn = warp & 3;
  const int g = lane >> 2, tig = lane & 3;
  const int m0 = blockIdx.y << 7, n0 = blockIdx.x << 7;

  float acc[4][4][4];
  gemm_tile_compute(A, BT, smh, m0, n0, K, acc);

#pragma unroll
  for (int mt = 0; mt < 4; mt++) {
    const int r = m0 + wm * 64 + mt * 16 + g;
#pragma unroll
    for (int nt = 0; nt < 4; nt++) {
      const int c = n0 + wn * 32 + nt * 8 + 2 * tig;
      const float b0 = __ldg(bias + c), b1 = __ldg(bias + c + 1);
      float2 v0 = {acc[mt][nt][0] + b0, acc[mt][nt][1] + b1};
      float2 v1 = {acc[mt][nt][2] + b0, acc[mt][nt][3] + b1};
      *(float2*)(C + (size_t)r * N + c) = v0;
      *(float2*)(C + (size_t)(r + 8) * N + c) = v1;
    }
  }
}

// ---------------- QKV GEMM with fused RoPE/split epilogue -------------------
// Q: rotated, /8, perm16, [B,H,L,Dh]. K: rotated, perm16. V: [B,H,Dh,L].
__global__ __launch_bounds__(256) void gemm_qkv_rope_kernel(
    const __half* __restrict__ A, const __half* __restrict__ BT,
    const float* __restrict__ bias, __half* __restrict__ Q,
    __half* __restrict__ K, __half* __restrict__ V) {
  extern __shared__ __half smh[];
  const int tid = threadIdx.x;
  const int warp = tid >> 5, lane = tid & 31;
  const int wm = warp >> 2, wn = warp & 3;
  const int g = lane >> 2, tig = lane & 3;
  const int m0 = blockIdx.y << 7, n0 = blockIdx.x << 7;

  float acc[4][4][4];
  gemm_tile_compute(A, BT, smh, m0, n0, EMBD, acc);

  const int seg = n0 >> 10;  // 0=q, 1=k, 2=v (block-uniform)

#pragma unroll
  for (int mt = 0; mt < 4; mt++) {
    const int r = m0 + wm * 64 + mt * 16 + g;  // token row (and r+8)
#pragma unroll
    for (int nt = 0; nt < 4; nt++) {
      const int c = n0 + wn * 32 + nt * 8 + 2 * tig;  // even column
      const float b0 = __ldg(bias + c), b1 = __ldg(bias + c + 1);
      const int d = c & 63;            // dim within head (even)
      const int h = (c & 1023) >> 6;   // head
      const int i = d >> 1;            // rope pair index
      float vals[2][2] = {{acc[mt][nt][0] + b0, acc[mt][nt][1] + b1},
                          {acc[mt][nt][2] + b0, acc[mt][nt][3] + b1}};
#pragma unroll
      for (int rr = 0; rr < 2; rr++) {
        const int m = r + rr * 8;
        const int bb = m >> 11, l = m & 2047;
        const float x1 = vals[rr][0], x2 = vals[rr][1];
        if (seg == 2) {
          __half* vp = V + ((size_t)(bb * NHEAD + h) * HDIM + d) * SEQ + l;
          vp[0] = __float2half_rn(x1);
          vp[SEQ] = __float2half_rn(x2);
        } else {
          const float2 cs = g_rope[l * 32 + i];
          float y1 = x1 * cs.x - x2 * cs.y;
          float y2 = x1 * cs.y + x2 * cs.x;
          if (seg == 0) { y1 *= 0.125f; y2 *= 0.125f; }
          const int j = (d & 15) >> 1;
          const int pd = (d & ~15) + (((j & 3) * 2 + (j >> 2)) << 1);
          __half* dp = (seg == 0 ? Q : K) +
                       ((size_t)(bb * NHEAD + h) * SEQ + l) * HDIM + pd;
          *(__half2*)dp = __floats2half2_rn(y1, y2);
        }
      }
    }
  }
}

// ---------------- fp16 tensor-core causal flash attention -------------------
// 128 q-rows per block, 8 warps, BN=64 keys/tile, double-buffered cp.async.
#define KS_H 80    // K tile row stride (halves)
#define VT_H 72    // Vt tile row stride
#define PS_H 72    // P/Q staging stride
#define KBUF_H (64 * KS_H)
#define VBUF_H (64 * VT_H)
#define PS_BUF_H (128 * PS_H)
#define FLASH_SMEM ((2 * KBUF_H + 2 * VBUF_H + PS_BUF_H) * 2 + 2 * 64 * 4)

__global__ __launch_bounds__(256, 2) void flash_mma_kernel(
    const __half* __restrict__ Q, const __half* __restrict__ K,
    const __half* __restrict__ V, const int* __restrict__ amask,
    __half* __restrict__ O) {
  extern __shared__ __half smh[];
  __half* Ksb = smh;
  __half* Vtb = Ksb + 2 * KBUF_H;
  __half* Ps = Vtb + 2 * VBUF_H;
  int* msk = (int*)(Ps + PS_BUF_H);  // [2][64]

  const int tid = threadIdx.x;
  const int warp = tid >> 5, lane = tid & 31;
  const int g = lane >> 2, tig = lane & 3;
  const int bx = (int)(gridDim.x - 1 - blockIdx.x);  // heavy blocks first
  const int h = blockIdx.y, b = blockIdx.z;
  const int q0 = bx << 7;
  const size_t base = (size_t)(b * NHEAD + h) * SEQ * HDIM;
  const size_t vbase = (size_t)(b * NHEAD + h) * HDIM * SEQ;

  // ---- stage Q tile (128x64 halves) through Ps, hoist fragments ----
#pragma unroll
  for (int i = 0; i < 4; i++) {
    const int p = tid + (i << 8);
    const int r = p >> 3, c = (p & 7) << 3;
    *(uint4*)(Ps + r * PS_H + c) =
        *(const uint4*)(Q + base + (size_t)(q0 + r) * HDIM + c);
  }
  __syncthreads();
  uint32_t qf[4][4];
  {
    const __half* qb = Ps + (warp * 16 + g) * PS_H;
#pragma unroll
    for (int ks = 0; ks < 4; ks++) {
      const int off = ks * 16 + 4 * tig;
      uint2 q02 = *(const uint2*)(qb + off);
      uint2 q13 = *(const uint2*)(qb + 8 * PS_H + off);
      qf[ks][0] = q02.x;
      qf[ks][2] = q02.y;
      qf[ks][1] = q13.x;
      qf[ks][3] = q13.y;
    }
  }
  __syncthreads();  // Ps becomes per-warp P staging

  auto prefetch = [&](int kt, int buf) {
    const int k0 = kt << 6;
    __half* Ks_ = Ksb + buf * KBUF_H;
    __half* Vt_ = Vtb + buf * VBUF_H;
#pragma unroll
    for (int i = 0; i < 2; i++) {
      const int p = tid + (i << 8);
      const int r = p >> 3, c = (p & 7) << 3;  // 64 rows x 8 16B-chunks
      uint32_t dk = (uint32_t)__cvta_generic_to_shared(Ks_ + r * KS_H + c);
      CPA16(dk, K + base + (size_t)(k0 + r) * HDIM + c);
      uint32_t dv = (uint32_t)__cvta_generic_to_shared(Vt_ + r * VT_H + c);
      CPA16(dv, V + vbase + (size_t)r * SEQ + k0 + c);
    }
    if (tid < 64) msk[buf * 64 + tid] = amask[b * SEQ + k0 + tid];
  };

  float m0 = -1e30f, m1 = -1e30f, l0 = 0.0f, l1 = 0.0f;
  float o[8][4];
#pragma unroll
  for (int nt = 0; nt < 8; nt++)
#pragma unroll
    for (int c = 0; c < 4; c++) o[nt][c] = 0.0f;

  const int NT = (q0 >> 6) + 2;
  const int rg0 = q0 + warp * 16 + g;

  prefetch(0, 0);
  asm volatile("cp.async.commit_group;\n");

  for (int kt = 0; kt < NT; kt++) {
    const int buf = kt & 1;
    if (kt + 1 < NT) prefetch(kt + 1, buf ^ 1);
    asm volatile("cp.async.commit_group;\n");
    asm volatile("cp.async.wait_group 1;\n");
    __syncthreads();

    const __half* Ks_ = Ksb + buf * KBUF_H;
    const __half* Vt_ = Vtb + buf * VBUF_H;
    const int* mk = msk + buf * 64;

    // ---- S = (Q/8) @ K^T  (fp16 mma, K=64 over 4 steps) ----
    float s[8][4];
#pragma unroll
    for (int nt = 0; nt < 8; nt++)
#pragma unroll
      for (int c = 0; c < 4; c++) s[nt][c] = 0.0f;

#pragma unroll
    for (int ks = 0; ks < 4; ks++) {
      const int off = ks * 16 + 4 * tig;
#pragma unroll
      for (int nt = 0; nt < 8; nt++) {
        uint2 bv = *(const uint2*)(Ks_ + (nt * 8 + g) * KS_H + off);
        uint32_t bf[2] = {bv.x, bv.y};
        mma_f16(s[nt], qf[ks], bf);
      }
    }

    // ---- mask ----
    if (kt >= NT - 2) {
      const int k0 = kt << 6;
#pragma unroll
      for (int nt = 0; nt < 8; nt++) {
        const int cg = k0 + nt * 8 + 2 * tig;
        const int m_a = mk[nt * 8 + 2 * tig], m_b = mk[nt * 8 + 2 * tig + 1];
        if (!(m_a && cg <= rg0)) s[nt][0] = -1e30f;
        if (!(m_b && cg + 1 <= rg0)) s[nt][1] = -1e30f;
        if (!(m_a && cg <= rg0 + 8)) s[nt][2] = -1e30f;
        if (!(m_b && cg + 1 <= rg0 + 8)) s[nt][3] = -1e30f;
      }
    } else {
#pragma unroll
      for (int nt = 0; nt < 8; nt++) {
        const int m_a = mk[nt * 8 + 2 * tig], m_b = mk[nt * 8 + 2 * tig + 1];
        if (!m_a) { s[nt][0] = -1e30f; s[nt][2] = -1e30f; }
        if (!m_b) { s[nt][1] = -1e30f; s[nt][3] = -1e30f; }
      }
    }

    // ---- online softmax ----
    float mx0 = -1e30f, mx1 = -1e30f;
#pragma unroll
    for (int nt = 0; nt < 8; nt++) {
      mx0 = fmaxf(mx0, fmaxf(s[nt][0], s[nt][1]));
      mx1 = fmaxf(mx1, fmaxf(s[nt][2], s[nt][3]));
    }
    mx0 = fmaxf(mx0, __shfl_xor_sync(0xffffffffu, mx0, 1));
    mx0 = fmaxf(mx0, __shfl_xor_sync(0xffffffffu, mx0, 2));
    mx1 = fmaxf(mx1, __shfl_xor_sync(0xffffffffu, mx1, 1));
    mx1 = fmaxf(mx1, __shfl_xor_sync(0xffffffffu, mx1, 2));
    const float nm0 = fmaxf(m0, mx0), nm1 = fmaxf(m1, mx1);
    const float corr0 = __expf(m0 - nm0), corr1 = __expf(m1 - nm1);
    m0 = nm0;
    m1 = nm1;

    float sum0 = 0.0f, sum1 = 0.0f;
#pragma unroll
    for (int nt = 0; nt < 8; nt++) {
      s[nt][0] = __expf(s[nt][0] - nm0);
      s[nt][1] = __expf(s[nt][1] - nm0);
      s[nt][2] = __expf(s[nt][2] - nm1);
      s[nt][3] = __expf(s[nt][3] - nm1);
      sum0 += s[nt][0] + s[nt][1];
      sum1 += s[nt][2] + s[nt][3];
    }
    sum0 += __shfl_xor_sync(0xffffffffu, sum0, 1);
    sum0 += __shfl_xor_sync(0xffffffffu, sum0, 2);
    sum1 += __shfl_xor_sync(0xffffffffu, sum1, 1);
    sum1 += __shfl_xor_sync(0xffffffffu, sum1, 2);
    l0 = l0 * corr0 + sum0;
    l1 = l1 * corr1 + sum1;

#pragma unroll
    for (int nt = 0; nt < 8; nt++) {
      o[nt][0] *= corr0;
      o[nt][1] *= corr0;
      o[nt][2] *= corr1;
      o[nt][3] *= corr1;
    }

    // ---- stage P as fp16 (C-layout -> A-layout) in per-warp Ps region ----
    __half* pr = Ps + (warp * 16 + g) * PS_H;
#pragma unroll
    for (int nt = 0; nt < 8; nt++) {
      const int c0 = nt * 8 + 2 * tig;
      *(__half2*)(pr + c0) = __floats2half2_rn(s[nt][0], s[nt][1]);
      *(__half2*)(pr + 8 * PS_H + c0) = __floats2half2_rn(s[nt][2], s[nt][3]);
    }
    __syncwarp();

    // ---- O += P @ V  (fp16 mma, K=64 keys over 4 steps) ----
    const __half* pb = Ps + (warp * 16 + g) * PS_H;
#pragma unroll
    for (int ks = 0; ks < 4; ks++) {
      const int off = ks * 16 + 2 * tig;
      uint32_t a[4];
      a[0] = *(const uint32_t*)(pb + off);
      a[1] = *(const uint32_t*)(pb + 8 * PS_H + off);
      a[2] = *(const uint32_t*)(pb + off + 8);
      a[3] = *(const uint32_t*)(pb + 8 * PS_H + off + 8);
#pragma unroll
      for (int nt = 0; nt < 8; nt++) {
        const __half* vb = Vt_ + (nt * 8 + g) * VT_H + off;
        uint32_t bf[2];
        bf[0] = *(const uint32_t*)(vb);
        bf[1] = *(const uint32_t*)(vb + 8);
        mma_f16(o[nt], a, bf);
      }
    }
    __syncthreads();  // all warps done with tiles[buf] before refill
  }

  // ---- write O fp16 perm16 to [B, L, H*Dh] for the proj GEMM ----
  const float inv0 = 1.0f / l0, inv1 = 1.0f / l1;
#pragma unroll
  for (int nt = 0; nt < 8; nt++) {
    const int dl = nt * 8 + 2 * tig;
    const int j = (dl & 15) >> 1;
    const int col = h * HDIM + (dl & ~15) + (((j & 3) * 2 + (j >> 2)) << 1);
    *(__half2*)(O + (size_t)(b * SEQ + rg0) * EMBD + col) =
        __floats2half2_rn(o[nt][0] * inv0, o[nt][1] * inv0);
    *(__half2*)(O + (size_t)(b * SEQ + rg0 + 8) * EMBD + col) =
        __floats2half2_rn(o[nt][2] * inv1, o[nt][3] * inv1);
  }
}

// ---------------------------------------------------------------------------
extern "C" void kernel_launch(void* const* d_in, const int* in_sizes, int n_in,
                              void* d_out, int out_size) {
  const float* x     = (const float*)d_in[0];
  const float* Wqkv  = (const float*)d_in[1];
  const float* bqkv  = (const float*)d_in[2];
  const float* Wproj = (const float*)d_in[3];
  const float* bproj = (const float*)d_in[4];
  const int*   amask = (const int*)d_in[5];
  float* out = (float*)d_out;

  __half *q, *k, *v, *att, *xh, *wqkvT, *wprojT;
  cudaGetSymbolAddress((void**)&q, g_q);
  cudaGetSymbolAddress((void**)&k, g_k);
  cudaGetSymbolAddress((void**)&v, g_v);
  cudaGetSymbolAddress((void**)&att, g_att);
  cudaGetSymbolAddress((void**)&xh, g_xh);
  cudaGetSymbolAddress((void**)&wqkvT, g_wqkvT);
  cudaGetSymbolAddress((void**)&wprojT, g_wprojT);

  cudaFuncSetAttribute(gemm_f16_kernel,
                       cudaFuncAttributeMaxDynamicSharedMemorySize, GEMM_SMEM);
  cudaFuncSetAttribute(gemm_qkv_rope_kernel,
                       cudaFuncAttributeMaxDynamicSharedMemorySize, GEMM_SMEM);
  cudaFuncSetAttribute(flash_mma_kernel,
                       cudaFuncAttributeMaxDynamicSharedMemorySize, FLASH_SMEM);

  // 0. RoPE table + operand preparation (fp16 round / permute / transpose)
  rope_table_kernel<<<SEQ * 32 / 256, 256>>>();
  round_permute_half<<<1184, 256>>>(x, xh, TOKENS * EMBD / 16);
  {
    dim3 gt1(QKVDIM / 32, EMBD / 32);
    transpose_permute_half<<<gt1, dim3(32, 8)>>>(Wqkv, wqkvT, EMBD, QKVDIM);
    dim3 gt2(EMBD / 32, EMBD / 32);
    transpose_permute_half<<<gt2, dim3(32, 8)>>>(Wproj, wprojT, EMBD, EMBD);
  }

  // 1. QKV projection + fused RoPE/split -> q (/8), k, v
  dim3 g1(QKVDIM / 128, TOKENS / 128);
  gemm_qkv_rope_kernel<<<g1, 256, GEMM_SMEM>>>(xh, wqkvT, bqkv, q, k, v);

  // 2. Causal flash attention (fp16 tensor cores) -> att (fp16, perm16)
  dim3 g3(SEQ / 128, NHEAD, BATCH);
  flash_mma_kernel<<<g3, 256, FLASH_SMEM>>>(q, k, v, amask, att);

  // 3. Output projection -> fp32 out
  dim3 g4(EMBD / 128, TOKENS / 128);
  gemm_f16_kernel<<<g4, 256, GEMM_SMEM>>>(att, wprojT, bproj, out, EMBD, EMBD);
}

// round 11
// speedup vs baseline: 1.0612x; 1.0612x over previous
#include <cuda_runtime.h>
#include <cuda_fp16.h>
#include <math.h>
#include <cstdint>

// Problem constants: B=4, L=2048, D=1024, H=16, Dh=64, 3D=3072
#define BATCH   4
#define SEQ     2048
#define EMBD    1024
#define NHEAD   16
#define HDIM    64
#define TOKENS  (BATCH * SEQ)            // 8192
#define QKVDIM  (3 * EMBD)               // 3072

// ---------------- scratch (static __device__, no allocation) ----------------
__device__ __half g_q[(size_t)BATCH * NHEAD * SEQ * HDIM];  // [B,H,L,Dh] /8, perm16
__device__ __half g_k[(size_t)BATCH * NHEAD * SEQ * HDIM];  // perm16
__device__ __half g_v[(size_t)BATCH * NHEAD * HDIM * SEQ];  // [B,H,Dh,L]
__device__ __half g_att[(size_t)TOKENS * EMBD];             // [B,L,D] perm16
__device__ float2 g_rope[(size_t)SEQ * 32];                 // cos/sin table
__device__ __half g_xh[(size_t)TOKENS * EMBD];              // x fp16, perm16
__device__ __half g_wqkvT[(size_t)QKVDIM * EMBD];           // W_qkv^T fp16, perm16
__device__ __half g_wprojT[(size_t)EMBD * EMBD];            // W_proj^T fp16, perm16

// ---------------- helpers ---------------------------------------------------
__device__ __forceinline__ void mma_f16(float* d, const uint32_t* a,
                                        const uint32_t* b) {
  asm volatile(
      "mma.sync.aligned.m16n8k16.row.col.f32.f16.f16.f32 "
      "{%0,%1,%2,%3},{%4,%5,%6,%7},{%8,%9},{%0,%1,%2,%3};"
      : "+f"(d[0]), "+f"(d[1]), "+f"(d[2]), "+f"(d[3])
      : "r"(a[0]), "r"(a[1]), "r"(a[2]), "r"(a[3]), "r"(b[0]), "r"(b[1]));
}

#define CPA16(dst, src) \
  asm volatile("cp.async.cg.shared.global [%0], [%1], 16;\n" ::"r"(dst), "l"(src))

// 16-group permutation: pair j (0..7) goes to pair position (j&3)*2 + (j>>2).
// Thread tig then finds k={2t,2t+1,2t+8,2t+9} contiguous at offset 4t.
__device__ __host__ __forceinline__ int perm16(int k) {
  const int j = (k & 15) >> 1;
  return (k & ~15) + (((j & 3) * 2 + (j >> 2)) << 1) + (k & 1);
}

// ---------------- RoPE cos/sin table ----------------------------------------
__global__ __launch_bounds__(256) void rope_table_kernel() {
  const int idx = blockIdx.x * 256 + threadIdx.x;  // 0..65535
  const int l = idx >> 5, i = idx & 31;
  const float inv_freq = 1.0f / powf(10000.0f, (2.0f * (float)i) / 64.0f);
  float s, c;
  sincosf((float)l * inv_freq, &s, &c);
  g_rope[idx] = make_float2(c, s);
}

// ------------- fp16 round + 16-group permute (A operands) -------------------
__global__ __launch_bounds__(256) void round_permute_half(
    const float* __restrict__ in, __half* __restrict__ out, int n16) {
  int i = blockIdx.x * 256 + threadIdx.x;  // one 16-float group per thread
  const int stride = gridDim.x * 256;
  for (; i < n16; i += stride) {
    const float4* ip = (const float4*)(in + 16 * (size_t)i);
    float v[16];
    *(float4*)(v + 0) = ip[0];
    *(float4*)(v + 4) = ip[1];
    *(float4*)(v + 8) = ip[2];
    *(float4*)(v + 12) = ip[3];
    __half h[16];
#pragma unroll
    for (int j = 0; j < 8; j++) {
      const int pp = (j & 3) * 2 + (j >> 2);
      h[pp * 2] = __float2half_rn(v[2 * j]);
      h[pp * 2 + 1] = __float2half_rn(v[2 * j + 1]);
    }
    uint4* op = (uint4*)(out + 16 * (size_t)i);
    op[0] = *(uint4*)(h);
    op[1] = *(uint4*)(h + 8);
  }
}

// ------------- transpose + fp16 round + permute (B/weight operands) ---------
// in: [K][N] row-major -> out: [N][K] fp16, k 16-group permuted
__global__ __launch_bounds__(256) void transpose_permute_half(
    const float* __restrict__ in, __half* __restrict__ out, int K, int N) {
  __shared__ float tile[32][33];
  const int k0 = blockIdx.y * 32, n0 = blockIdx.x * 32;
  const int tx = threadIdx.x, ty = threadIdx.y;  // 32 x 8
#pragma unroll
  for (int i = 0; i < 32; i += 8)
    tile[ty + i][tx] = in[(size_t)(k0 + ty + i) * N + n0 + tx];
  __syncthreads();
  const int pk = perm16(tx);
#pragma unroll
  for (int i = 0; i < 32; i += 8) {
    const int n = ty + i;
    out[(size_t)(n0 + n) * K + k0 + pk] = __float2half_rn(tile[tx][n]);
  }
}

// ---------------- GEMM core (fp16 operands, fp32 accum) ---------------------
// A: [M][K] perm16; BT: [N][K] perm16. BK=64. 128x128 tile, 256 threads.
#define ABS_H 80                        // smem row stride in halves (160B)
#define AB_BUF_H (128 * ABS_H)          // 10240 halves
#define GEMM_SMEM (4 * AB_BUF_H * 2)    // 81920 B

__device__ __forceinline__ void gemm_tile_compute(
    const __half* __restrict__ A, const __half* __restrict__ BT, __half* sm,
    int m0, int n0, int K, float acc[4][4][4]) {
  const int tid = threadIdx.x;
  const int warp = tid >> 5, lane = tid & 31;
  const int wm = warp >> 2, wn = warp & 3;
  const int g = lane >> 2, tig = lane & 3;

#pragma unroll
  for (int i = 0; i < 4; i++)
#pragma unroll
    for (int j = 0; j < 4; j++)
#pragma unroll
      for (int t = 0; t < 4; t++) acc[i][j][t] = 0.0f;

  auto prefetch = [&](int kt, int buf) {
    __half* As = sm + buf * AB_BUF_H;
    __half* Bs = sm + 2 * AB_BUF_H + buf * AB_BUF_H;
    const int k0 = kt << 6;
#pragma unroll
    for (int j = 0; j < 4; j++) {
      const int p = tid + (j << 8);
      const int r = p >> 3, c = (p & 7) << 3;  // 128 rows x 8 16B-chunks
      uint32_t da = (uint32_t)__cvta_generic_to_shared(As + r * ABS_H + c);
      CPA16(da, A + (size_t)(m0 + r) * K + k0 + c);
      uint32_t db = (uint32_t)__cvta_generic_to_shared(Bs + r * ABS_H + c);
      CPA16(db, BT + (size_t)(n0 + r) * K + k0 + c);
    }
    asm volatile("cp.async.commit_group;\n");
  };

  const int NT = K >> 6;
  prefetch(0, 0);

  for (int kt = 0; kt < NT; kt++) {
    const int buf = kt & 1;
    if (kt + 1 < NT) {
      prefetch(kt + 1, buf ^ 1);
      asm volatile("cp.async.wait_group 1;\n");
    } else {
      asm volatile("cp.async.wait_group 0;\n");
    }
    __syncthreads();

    const __half* As = sm + buf * AB_BUF_H;
    const __half* Bs = sm + 2 * AB_BUF_H + buf * AB_BUF_H;

#pragma unroll
    for (int ks = 0; ks < 4; ks++) {
      const int koff = ks * 16 + 4 * tig;
      uint32_t af[4][4], bf[4][2];
#pragma unroll
      for (int mt = 0; mt < 4; mt++) {
        const int row = wm * 64 + mt * 16 + g;
        uint2 a02 = *(const uint2*)(As + row * ABS_H + koff);
        uint2 a13 = *(const uint2*)(As + (row + 8) * ABS_H + koff);
        af[mt][0] = a02.x;
        af[mt][2] = a02.y;
        af[mt][1] = a13.x;
        af[mt][3] = a13.y;
      }
#pragma unroll
      for (int nt = 0; nt < 4; nt++) {
        const int nrow = wn * 32 + nt * 8 + g;
        uint2 b01 = *(const uint2*)(Bs + nrow * ABS_H + koff);
        bf[nt][0] = b01.x;
        bf[nt][1] = b01.y;
      }
#pragma unroll
      for (int mt = 0; mt < 4; mt++)
#pragma unroll
        for (int nt = 0; nt < 4; nt++) mma_f16(acc[mt][nt], af[mt], bf[nt]);
    }
    __syncthreads();
  }
}

// ---------------- plain GEMM + bias (proj, fp32 out) ------------------------
__global__ __launch_bounds__(256) void gemm_f16_kernel(
    const __half* __restrict__ A, const __half* __restrict__ BT,
    const float* __restrict__ bias, float* __restrict__ C, int N, int K) {
  extern __shared__ __half smh[];
  const int tid = threadIdx.x;
  const int warp = tid >> 5, lane = tid & 31;
  const int wm = warp >> 2, wn = warp & 3;
  const int g = lane >> 2, tig = lane & 3;
  const int m0 = blockIdx.y << 7, n0 = blockIdx.x << 7;

  float acc[4][4][4];
  gemm_tile_compute(A, BT, smh, m0, n0, K, acc);

#pragma unroll
  for (int mt = 0; mt < 4; mt++) {
    const int r = m0 + wm * 64 + mt * 16 + g;
#pragma unroll
    for (int nt = 0; nt < 4; nt++) {
      const int c = n0 + wn * 32 + nt * 8 + 2 * tig;
      const float b0 = __ldg(bias + c), b1 = __ldg(bias + c + 1);
      float2 v0 = {acc[mt][nt][0] + b0, acc[mt][nt][1] + b1};
      float2 v1 = {acc[mt][nt][2] + b0, acc[mt][nt][3] + b1};
      *(float2*)(C + (size_t)r * N + c) = v0;
      *(float2*)(C + (size_t)(r + 8) * N + c) = v1;
    }
  }
}

// ---------------- QKV GEMM with fused RoPE/split epilogue -------------------
// Q: rotated, /8, perm16, [B,H,L,Dh]. K: rotated, perm16. V: [B,H,Dh,L].
__global__ __launch_bounds__(256) void gemm_qkv_rope_kernel(
    const __half* __restrict__ A, const __half* __restrict__ BT,
    const float* __restrict__ bias, __half* __restrict__ Q,
    __half* __restrict__ K, __half* __restrict__ V) {
  extern __shared__ __half smh[];
  const int tid = threadIdx.x;
  const int warp = tid >> 5, lane = tid & 31;
  const int wm = warp >> 2, wn = warp & 3;
  const int g = lane >> 2, tig = lane & 3;
  const int m0 = blockIdx.y << 7, n0 = blockIdx.x << 7;

  float acc[4][4][4];
  gemm_tile_compute(A, BT, smh, m0, n0, EMBD, acc);

  const int seg = n0 >> 10;  // 0=q, 1=k, 2=v (block-uniform)

#pragma unroll
  for (int mt = 0; mt < 4; mt++) {
    const int r = m0 + wm * 64 + mt * 16 + g;  // token row (and r+8)
#pragma unroll
    for (int nt = 0; nt < 4; nt++) {
      const int c = n0 + wn * 32 + nt * 8 + 2 * tig;  // even column
      const float b0 = __ldg(bias + c), b1 = __ldg(bias + c + 1);
      const int d = c & 63;            // dim within head (even)
      const int h = (c & 1023) >> 6;   // head
      const int i = d >> 1;            // rope pair index
      float vals[2][2] = {{acc[mt][nt][0] + b0, acc[mt][nt][1] + b1},
                          {acc[mt][nt][2] + b0, acc[mt][nt][3] + b1}};
#pragma unroll
      for (int rr = 0; rr < 2; rr++) {
        const int m = r + rr * 8;
        const int bb = m >> 11, l = m & 2047;
        const float x1 = vals[rr][0], x2 = vals[rr][1];
        if (seg == 2) {
          __half* vp = V + ((size_t)(bb * NHEAD + h) * HDIM + d) * SEQ + l;
          vp[0] = __float2half_rn(x1);
          vp[SEQ] = __float2half_rn(x2);
        } else {
          const float2 cs = g_rope[l * 32 + i];
          float y1 = x1 * cs.x - x2 * cs.y;
          float y2 = x1 * cs.y + x2 * cs.x;
          if (seg == 0) { y1 *= 0.125f; y2 *= 0.125f; }
          const int j = (d & 15) >> 1;
          const int pd = (d & ~15) + (((j & 3) * 2 + (j >> 2)) << 1);
          __half* dp = (seg == 0 ? Q : K) +
                       ((size_t)(bb * NHEAD + h) * SEQ + l) * HDIM + pd;
          *(__half2*)dp = __floats2half2_rn(y1, y2);
        }
      }
    }
  }
}

// ---------------- fp16 tensor-core causal flash attention -------------------
// 128 q-rows per block, 8 warps, BN=64 keys/tile, double-buffered cp.async.
#define KS_H 80    // K tile row stride (halves)
#define VT_H 72    // Vt tile row stride
#define PS_H 72    // P/Q staging stride
#define KBUF_H (64 * KS_H)
#define VBUF_H (64 * VT_H)
#define PS_BUF_H (128 * PS_H)
#define FLASH_SMEM ((2 * KBUF_H + 2 * VBUF_H + PS_BUF_H) * 2 + 2 * 64 * 4)

__global__ __launch_bounds__(256, 2) void flash_mma_kernel(
    const __half* __restrict__ Q, const __half* __restrict__ K,
    const __half* __restrict__ V, const int* __restrict__ amask,
    __half* __restrict__ O) {
  extern __shared__ __half smh[];
  __half* Ksb = smh;
  __half* Vtb = Ksb + 2 * KBUF_H;
  __half* Ps = Vtb + 2 * VBUF_H;
  int* msk = (int*)(Ps + PS_BUF_H);  // [2][64]

  const int tid = threadIdx.x;
  const int warp = tid >> 5, lane = tid & 31;
  const int g = lane >> 2, tig = lane & 3;
  const int bx = (int)(gridDim.x - 1 - blockIdx.x);  // heavy blocks first
  const int h = blockIdx.y, b = blockIdx.z;
  const int q0 = bx << 7;
  const size_t base = (size_t)(b * NHEAD + h) * SEQ * HDIM;
  const size_t vbase = (size_t)(b * NHEAD + h) * HDIM * SEQ;

  // ---- stage Q tile (128x64 halves) through Ps, hoist fragments ----
#pragma unroll
  for (int i = 0; i < 4; i++) {
    const int p = tid + (i << 8);
    const int r = p >> 3, c = (p & 7) << 3;
    *(uint4*)(Ps + r * PS_H + c) =
        *(const uint4*)(Q + base + (size_t)(q0 + r) * HDIM + c);
  }
  __syncthreads();
  uint32_t qf[4][4];
  {
    const __half* qb = Ps + (warp * 16 + g) * PS_H;
#pragma unroll
    for (int ks = 0; ks < 4; ks++) {
      const int off = ks * 16 + 4 * tig;
      uint2 q02 = *(const uint2*)(qb + off);
      uint2 q13 = *(const uint2*)(qb + 8 * PS_H + off);
      qf[ks][0] = q02.x;
      qf[ks][2] = q02.y;
      qf[ks][1] = q13.x;
      qf[ks][3] = q13.y;
    }
  }
  __syncthreads();  // Ps becomes per-warp P staging

  auto prefetch = [&](int kt, int buf) {
    const int k0 = kt << 6;
    __half* Ks_ = Ksb + buf * KBUF_H;
    __half* Vt_ = Vtb + buf * VBUF_H;
#pragma unroll
    for (int i = 0; i < 2; i++) {
      const int p = tid + (i << 8);
      const int r = p >> 3, c = (p & 7) << 3;
      uint32_t dk = (uint32_t)__cvta_generic_to_shared(Ks_ + r * KS_H + c);
      CPA16(dk, K + base + (size_t)(k0 + r) * HDIM + c);
      uint32_t dv = (uint32_t)__cvta_generic_to_shared(Vt_ + r * VT_H + c);
      CPA16(dv, V + vbase + (size_t)r * SEQ + k0 + c);
    }
    if (tid < 64) msk[buf * 64 + tid] = amask[b * SEQ + k0 + tid];
  };

  float m0 = -1e30f, m1 = -1e30f, l0 = 0.0f, l1 = 0.0f;
  float o[8][4];
#pragma unroll
  for (int nt = 0; nt < 8; nt++)
#pragma unroll
    for (int c = 0; c < 4; c++) o[nt][c] = 0.0f;

  const int NT = (q0 >> 6) + 2;
  const int rg0 = q0 + warp * 16 + g;

  prefetch(0, 0);
  asm volatile("cp.async.commit_group;\n");

  for (int kt = 0; kt < NT; kt++) {
    const int buf = kt & 1;
    if (kt + 1 < NT) prefetch(kt + 1, buf ^ 1);
    asm volatile("cp.async.commit_group;\n");
    asm volatile("cp.async.wait_group 1;\n");
    __syncthreads();

    const __half* Ks_ = Ksb + buf * KBUF_H;
    const __half* Vt_ = Vtb + buf * VBUF_H;
    const int* mk = msk + buf * 64;

    // ---- S = (Q/8) @ K^T ----
    float s[8][4];
#pragma unroll
    for (int nt = 0; nt < 8; nt++)
#pragma unroll
      for (int c = 0; c < 4; c++) s[nt][c] = 0.0f;

#pragma unroll
    for (int ks = 0; ks < 4; ks++) {
      const int off = ks * 16 + 4 * tig;
#pragma unroll
      for (int nt = 0; nt < 8; nt++) {
        uint2 bv = *(const uint2*)(Ks_ + (nt * 8 + g) * KS_H + off);
        uint32_t bf[2] = {bv.x, bv.y};
        mma_f16(s[nt], qf[ks], bf);
      }
    }

    // ---- mask ----
    if (kt >= NT - 2) {
      const int k0 = kt << 6;
#pragma unroll
      for (int nt = 0; nt < 8; nt++) {
        const int cg = k0 + nt * 8 + 2 * tig;
        const int m_a = mk[nt * 8 + 2 * tig], m_b = mk[nt * 8 + 2 * tig + 1];
        if (!(m_a && cg <= rg0)) s[nt][0] = -1e30f;
        if (!(m_b && cg + 1 <= rg0)) s[nt][1] = -1e30f;
        if (!(m_a && cg <= rg0 + 8)) s[nt][2] = -1e30f;
        if (!(m_b && cg + 1 <= rg0 + 8)) s[nt][3] = -1e30f;
      }
    } else {
#pragma unroll
      for (int nt = 0; nt < 8; nt++) {
        const int m_a = mk[nt * 8 + 2 * tig], m_b = mk[nt * 8 + 2 * tig + 1];
        if (!m_a) { s[nt][0] = -1e30f; s[nt][2] = -1e30f; }
        if (!m_b) { s[nt][1] = -1e30f; s[nt][3] = -1e30f; }
      }
    }

    // ---- online softmax ----
    float mx0 = -1e30f, mx1 = -1e30f;
#pragma unroll
    for (int nt = 0; nt < 8; nt++) {
      mx0 = fmaxf(mx0, fmaxf(s[nt][0], s[nt][1]));
      mx1 = fmaxf(mx1, fmaxf(s[nt][2], s[nt][3]));
    }
    mx0 = fmaxf(mx0, __shfl_xor_sync(0xffffffffu, mx0, 1));
    mx0 = fmaxf(mx0, __shfl_xor_sync(0xffffffffu, mx0, 2));
    mx1 = fmaxf(mx1, __shfl_xor_sync(0xffffffffu, mx1, 1));
    mx1 = fmaxf(mx1, __shfl_xor_sync(0xffffffffu, mx1, 2));
    const float nm0 = fmaxf(m0, mx0), nm1 = fmaxf(m1, mx1);
    const float corr0 = __expf(m0 - nm0), corr1 = __expf(m1 - nm1);
    m0 = nm0;
    m1 = nm1;

    float sum0 = 0.0f, sum1 = 0.0f;
#pragma unroll
    for (int nt = 0; nt < 8; nt++) {
      s[nt][0] = __expf(s[nt][0] - nm0);
      s[nt][1] = __expf(s[nt][1] - nm0);
      s[nt][2] = __expf(s[nt][2] - nm1);
      s[nt][3] = __expf(s[nt][3] - nm1);
      sum0 += s[nt][0] + s[nt][1];
      sum1 += s[nt][2] + s[nt][3];
    }
    sum0 += __shfl_xor_sync(0xffffffffu, sum0, 1);
    sum0 += __shfl_xor_sync(0xffffffffu, sum0, 2);
    sum1 += __shfl_xor_sync(0xffffffffu, sum1, 1);
    sum1 += __shfl_xor_sync(0xffffffffu, sum1, 2);
    l0 = l0 * corr0 + sum0;
    l1 = l1 * corr1 + sum1;

#pragma unroll
    for (int nt = 0; nt < 8; nt++) {
      o[nt][0] *= corr0;
      o[nt][1] *= corr0;
      o[nt][2] *= corr1;
      o[nt][3] *= corr1;
    }

    // ---- stage P as fp16 (C-layout -> A-layout) in per-warp Ps region ----
    __half* pr = Ps + (warp * 16 + g) * PS_H;
#pragma unroll
    for (int nt = 0; nt < 8; nt++) {
      const int c0 = nt * 8 + 2 * tig;
      *(__half2*)(pr + c0) = __floats2half2_rn(s[nt][0], s[nt][1]);
      *(__half2*)(pr + 8 * PS_H + c0) = __floats2half2_rn(s[nt][2], s[nt][3]);
    }
    __syncwarp();

    // ---- O += P @ V ----
    const __half* pb = Ps + (warp * 16 + g) * PS_H;
#pragma unroll
    for (int ks = 0; ks < 4; ks++) {
      const int off = ks * 16 + 2 * tig;
      uint32_t a[4];
      a[0] = *(const uint32_t*)(pb + off);
      a[1] = *(const uint32_t*)(pb + 8 * PS_H + off);
      a[2] = *(const uint32_t*)(pb + off + 8);
      a[3] = *(const uint32_t*)(pb + 8 * PS_H + off + 8);
#pragma unroll
      for (int nt = 0; nt < 8; nt++) {
        const __half* vb = Vt_ + (nt * 8 + g) * VT_H + off;
        uint32_t bf[2];
        bf[0] = *(const uint32_t*)(vb);
        bf[1] = *(const uint32_t*)(vb + 8);
        mma_f16(o[nt], a, bf);
      }
    }
    __syncthreads();  // all warps done with tiles[buf] before refill
  }

  // ---- write O fp16 perm16 to [B, L, H*Dh] for the proj GEMM ----
  const float inv0 = 1.0f / l0, inv1 = 1.0f / l1;
#pragma unroll
  for (int nt = 0; nt < 8; nt++) {
    const int dl = nt * 8 + 2 * tig;
    const int j = (dl & 15) >> 1;
    const int col = h * HDIM + (dl & ~15) + (((j & 3) * 2 + (j >> 2)) << 1);
    *(__half2*)(O + (size_t)(b * SEQ + rg0) * EMBD + col) =
        __floats2half2_rn(o[nt][0] * inv0, o[nt][1] * inv0);
    *(__half2*)(O + (size_t)(b * SEQ + rg0 + 8) * EMBD + col) =
        __floats2half2_rn(o[nt][2] * inv1, o[nt][3] * inv1);
  }
}

// ---------------------------------------------------------------------------
extern "C" void kernel_launch(void* const* d_in, const int* in_sizes, int n_in,
                              void* d_out, int out_size) {
  const float* x     = (const float*)d_in[0];
  const float* Wqkv  = (const float*)d_in[1];
  const float* bqkv  = (const float*)d_in[2];
  const float* Wproj = (const float*)d_in[3];
  const float* bproj = (const float*)d_in[4];
  const int*   amask = (const int*)d_in[5];
  float* out = (float*)d_out;

  __half *q, *k, *v, *att, *xh, *wqkvT, *wprojT;
  cudaGetSymbolAddress((void**)&q, g_q);
  cudaGetSymbolAddress((void**)&k, g_k);
  cudaGetSymbolAddress((void**)&v, g_v);
  cudaGetSymbolAddress((void**)&att, g_att);
  cudaGetSymbolAddress((void**)&xh, g_xh);
  cudaGetSymbolAddress((void**)&wqkvT, g_wqkvT);
  cudaGetSymbolAddress((void**)&wprojT, g_wprojT);

  cudaFuncSetAttribute(gemm_f16_kernel,
                       cudaFuncAttributeMaxDynamicSharedMemorySize, GEMM_SMEM);
  cudaFuncSetAttribute(gemm_qkv_rope_kernel,
                       cudaFuncAttributeMaxDynamicSharedMemorySize, GEMM_SMEM);
  cudaFuncSetAttribute(flash_mma_kernel,
                       cudaFuncAttributeMaxDynamicSharedMemorySize, FLASH_SMEM);

  // 0. RoPE table + operand preparation (fp16 round / permute / transpose)
  rope_table_kernel<<<SEQ * 32 / 256, 256>>>();
  round_permute_half<<<1184, 256>>>(x, xh, TOKENS * EMBD / 16);
  {
    dim3 gt1(QKVDIM / 32, EMBD / 32);
    transpose_permute_half<<<gt1, dim3(32, 8)>>>(Wqkv, wqkvT, EMBD, QKVDIM);
    dim3 gt2(EMBD / 32, EMBD / 32);
    transpose_permute_half<<<gt2, dim3(32, 8)>>>(Wproj, wprojT, EMBD, EMBD);
  }

  // 1. QKV projection + fused RoPE/split -> q (/8), k, v
  dim3 g1(QKVDIM / 128, TOKENS / 128);
  gemm_qkv_rope_kernel<<<g1, 256, GEMM_SMEM>>>(xh, wqkvT, bqkv, q, k, v);

  // 2. Causal flash attention (fp16 tensor cores) -> att (fp16, perm16)
  dim3 g3(SEQ / 128, NHEAD, BATCH);
  flash_mma_kernel<<<g3, 256, FLASH_SMEM>>>(q, k, v, amask, att);

  // 3. Output projection -> fp32 out
  dim3 g4(EMBD / 128, TOKENS / 128);
  gemm_f16_kernel<<<g4, 256, GEMM_SMEM>>>(att, wprojT, bproj, out, EMBD, EMBD);
}

// round 12
// speedup vs baseline: 1.1100x; 1.0460x over previous
#include <cuda_runtime.h>
#include <cuda_fp16.h>
#include <math.h>
#include <cstdint>

// Problem constants: B=4, L=2048, D=1024, H=16, Dh=64, 3D=3072
#define BATCH   4
#define SEQ     2048
#define EMBD    1024
#define NHEAD   16
#define HDIM    64
#define TOKENS  (BATCH * SEQ)            // 8192
#define QKVDIM  (3 * EMBD)               // 3072

// ---------------- scratch (static __device__, no allocation) ----------------
__device__ __half g_q[(size_t)BATCH * NHEAD * SEQ * HDIM];  // /8*log2e, perm16
__device__ __half g_k[(size_t)BATCH * NHEAD * SEQ * HDIM];  // perm16
__device__ __half g_v[(size_t)BATCH * NHEAD * HDIM * SEQ];  // [B,H,Dh,L]
__device__ __half g_att[(size_t)TOKENS * EMBD];             // [B,L,D] perm16
__device__ float2 g_rope[(size_t)SEQ * 32];                 // cos/sin table
__device__ __half g_xh[(size_t)TOKENS * EMBD];              // x fp16, perm16
__device__ __half g_wqkvT[(size_t)QKVDIM * EMBD];           // W_qkv^T fp16, perm16
__device__ __half g_wprojT[(size_t)EMBD * EMBD];            // W_proj^T fp16, perm16

// ---------------- helpers ---------------------------------------------------
__device__ __forceinline__ void mma_f16(float* d, const uint32_t* a,
                                        const uint32_t* b) {
  asm volatile(
      "mma.sync.aligned.m16n8k16.row.col.f32.f16.f16.f32 "
      "{%0,%1,%2,%3},{%4,%5,%6,%7},{%8,%9},{%0,%1,%2,%3};"
      : "+f"(d[0]), "+f"(d[1]), "+f"(d[2]), "+f"(d[3])
      : "r"(a[0]), "r"(a[1]), "r"(a[2]), "r"(a[3]), "r"(b[0]), "r"(b[1]));
}

#define CPA16(dst, src) \
  asm volatile("cp.async.cg.shared.global [%0], [%1], 16;\n" ::"r"(dst), "l"(src))

__device__ __forceinline__ float ex2f(float x) {
  float y;
  asm("ex2.approx.f32 %0, %1;" : "=f"(y) : "f"(x));
  return y;
}

// 16-group permutation: pair j (0..7) goes to pair position (j&3)*2 + (j>>2).
__device__ __host__ __forceinline__ int perm16(int k) {
  const int j = (k & 15) >> 1;
  return (k & ~15) + (((j & 3) * 2 + (j >> 2)) << 1) + (k & 1);
}

#define QSCALE (0.125f * 1.44269504f)   // 1/sqrt(64) * log2(e)

// ------------- fp16 round + perm16 (x) + RoPE table fill --------------------
__global__ __launch_bounds__(256) void round_permute_rope(
    const float* __restrict__ in, __half* __restrict__ out, int n16) {
  // blocks 0..255 additionally fill the 2048x32 rope table (65536 entries)
  if (blockIdx.x < 256) {
    const int idx = blockIdx.x * 256 + threadIdx.x;
    const int l = idx >> 5, i = idx & 31;
    const float inv_freq = 1.0f / powf(10000.0f, (2.0f * (float)i) / 64.0f);
    float s, c;
    sincosf((float)l * inv_freq, &s, &c);
    g_rope[idx] = make_float2(c, s);
  }
  int i = blockIdx.x * 256 + threadIdx.x;
  const int stride = gridDim.x * 256;
  for (; i < n16; i += stride) {
    const float4* ip = (const float4*)(in + 16 * (size_t)i);
    float v[16];
    *(float4*)(v + 0) = ip[0];
    *(float4*)(v + 4) = ip[1];
    *(float4*)(v + 8) = ip[2];
    *(float4*)(v + 12) = ip[3];
    __half h[16];
#pragma unroll
    for (int j = 0; j < 8; j++) {
      const int pp = (j & 3) * 2 + (j >> 2);
      h[pp * 2] = __float2half_rn(v[2 * j]);
      h[pp * 2 + 1] = __float2half_rn(v[2 * j + 1]);
    }
    uint4* op = (uint4*)(out + 16 * (size_t)i);
    op[0] = *(uint4*)(h);
    op[1] = *(uint4*)(h + 8);
  }
}

// ------------- both weight transposes in ONE launch -------------------------
// W [K][N] row-major -> out [N][K] fp16, k perm16.  x<96: Wqkv, else Wproj.
__global__ __launch_bounds__(256) void transpose_both_kernel(
    const float* __restrict__ Wqkv, __half* __restrict__ outQkv,
    const float* __restrict__ Wproj, __half* __restrict__ outProj) {
  __shared__ float tile[32][33];
  const float* in;
  __half* out;
  int N, bxx;
  if (blockIdx.x < 96) {
    in = Wqkv; out = outQkv; N = QKVDIM; bxx = blockIdx.x;
  } else {
    in = Wproj; out = outProj; N = EMBD; bxx = blockIdx.x - 96;
  }
  const int K = EMBD;
  const int k0 = blockIdx.y * 32, n0 = bxx * 32;
  const int tx = threadIdx.x, ty = threadIdx.y;  // 32 x 8
#pragma unroll
  for (int i = 0; i < 32; i += 8)
    tile[ty + i][tx] = in[(size_t)(k0 + ty + i) * N + n0 + tx];
  __syncthreads();
  const int pk = perm16(tx);
#pragma unroll
  for (int i = 0; i < 32; i += 8) {
    const int n = ty + i;
    out[(size_t)(n0 + n) * K + k0 + pk] = __float2half_rn(tile[tx][n]);
  }
}

// ---------------- GEMM core (fp16 operands, fp32 accum) ---------------------
// A: [M][K] perm16; BT: [N][K] perm16. BK=64. 128x128 tile, 256 threads.
#define ABS_H 80                        // smem row stride in halves (160B)
#define AB_BUF_H (128 * ABS_H)          // 10240 halves
#define GEMM_SMEM (4 * AB_BUF_H * 2)    // 81920 B

__device__ __forceinline__ void gemm_tile_compute(
    const __half* __restrict__ A, const __half* __restrict__ BT, __half* sm,
    int m0, int n0, int K, float acc[4][4][4]) {
  const int tid = threadIdx.x;
  const int warp = tid >> 5, lane = tid & 31;
  const int wm = warp >> 2, wn = warp & 3;
  const int g = lane >> 2, tig = lane & 3;

#pragma unroll
  for (int i = 0; i < 4; i++)
#pragma unroll
    for (int j = 0; j < 4; j++)
#pragma unroll
      for (int t = 0; t < 4; t++) acc[i][j][t] = 0.0f;

  auto prefetch = [&](int kt, int buf) {
    __half* As = sm + buf * AB_BUF_H;
    __half* Bs = sm + 2 * AB_BUF_H + buf * AB_BUF_H;
    const int k0 = kt << 6;
#pragma unroll
    for (int j = 0; j < 4; j++) {
      const int p = tid + (j << 8);
      const int r = p >> 3, c = (p & 7) << 3;  // 128 rows x 8 16B-chunks
      uint32_t da = (uint32_t)__cvta_generic_to_shared(As + r * ABS_H + c);
      CPA16(da, A + (size_t)(m0 + r) * K + k0 + c);
      uint32_t db = (uint32_t)__cvta_generic_to_shared(Bs + r * ABS_H + c);
      CPA16(db, BT + (size_t)(n0 + r) * K + k0 + c);
    }
    asm volatile("cp.async.commit_group;\n");
  };

  const int NT = K >> 6;
  prefetch(0, 0);

  for (int kt = 0; kt < NT; kt++) {
    const int buf = kt & 1;
    if (kt + 1 < NT) {
      prefetch(kt + 1, buf ^ 1);
      asm volatile("cp.async.wait_group 1;\n");
    } else {
      asm volatile("cp.async.wait_group 0;\n");
    }
    __syncthreads();

    const __half* As = sm + buf * AB_BUF_H;
    const __half* Bs = sm + 2 * AB_BUF_H + buf * AB_BUF_H;

#pragma unroll
    for (int ks = 0; ks < 4; ks++) {
      const int koff = ks * 16 + 4 * tig;
      uint32_t af[4][4], bf[4][2];
#pragma unroll
      for (int mt = 0; mt < 4; mt++) {
        const int row = wm * 64 + mt * 16 + g;
        uint2 a02 = *(const uint2*)(As + row * ABS_H + koff);
        uint2 a13 = *(const uint2*)(As + (row + 8) * ABS_H + koff);
        af[mt][0] = a02.x;
        af[mt][2] = a02.y;
        af[mt][1] = a13.x;
        af[mt][3] = a13.y;
      }
#pragma unroll
      for (int nt = 0; nt < 4; nt++) {
        const int nrow = wn * 32 + nt * 8 + g;
        uint2 b01 = *(const uint2*)(Bs + nrow * ABS_H + koff);
        bf[nt][0] = b01.x;
        bf[nt][1] = b01.y;
      }
#pragma unroll
      for (int mt = 0; mt < 4; mt++)
#pragma unroll
        for (int nt = 0; nt < 4; nt++) mma_f16(acc[mt][nt], af[mt], bf[nt]);
    }
    __syncthreads();
  }
}

// ---------------- plain GEMM + bias (proj, fp32 out) ------------------------
__global__ __launch_bounds__(256) void gemm_f16_kernel(
    const __half* __restrict__ A, const __half* __restrict__ BT,
    const float* __restrict__ bias, float* __restrict__ C, int N, int K) {
  extern __shared__ __half smh[];
  const int tid = threadIdx.x;
  const int warp = tid >> 5, lane = tid & 31;
  const int wm = warp >> 2, wn = warp & 3;
  const int g = lane >> 2, tig = lane & 3;
  const int m0 = blockIdx.y << 7, n0 = blockIdx.x << 7;

  float acc[4][4][4];
  gemm_tile_compute(A, BT, smh, m0, n0, K, acc);

#pragma unroll
  for (int mt = 0; mt < 4; mt++) {
    const int r = m0 + wm * 64 + mt * 16 + g;
#pragma unroll
    for (int nt = 0; nt < 4; nt++) {
      const int c = n0 + wn * 32 + nt * 8 + 2 * tig;
      const float b0 = __ldg(bias + c), b1 = __ldg(bias + c + 1);
      float2 v0 = {acc[mt][nt][0] + b0, acc[mt][nt][1] + b1};
      float2 v1 = {acc[mt][nt][2] + b0, acc[mt][nt][3] + b1};
      *(float2*)(C + (size_t)r * N + c) = v0;
      *(float2*)(C + (size_t)(r + 8) * N + c) = v1;
    }
  }
}

// ---------------- QKV GEMM with fused RoPE/split epilogue -------------------
// Q: rotated, *QSCALE, perm16, [B,H,L,Dh]. K: rotated, perm16. V: [B,H,Dh,L].
__global__ __launch_bounds__(256) void gemm_qkv_rope_kernel(
    const __half* __restrict__ A, const __half* __restrict__ BT,
    const float* __restrict__ bias, __half* __restrict__ Q,
    __half* __restrict__ K, __half* __restrict__ V) {
  extern __shared__ __half smh[];
  const int tid = threadIdx.x;
  const int warp = tid >> 5, lane = tid & 31;
  const int wm = warp >> 2, wn = warp & 3;
  const int g = lane >> 2, tig = lane & 3;
  const int m0 = blockIdx.y << 7, n0 = blockIdx.x << 7;

  float acc[4][4][4];
  gemm_tile_compute(A, BT, smh, m0, n0, EMBD, acc);

  const int seg = n0 >> 10;  // 0=q, 1=k, 2=v (block-uniform)

#pragma unroll
  for (int mt = 0; mt < 4; mt++) {
    const int r = m0 + wm * 64 + mt * 16 + g;  // token row (and r+8)
#pragma unroll
    for (int nt = 0; nt < 4; nt++) {
      const int c = n0 + wn * 32 + nt * 8 + 2 * tig;  // even column
      const float b0 = __ldg(bias + c), b1 = __ldg(bias + c + 1);
      const int d = c & 63;            // dim within head (even)
      const int h = (c & 1023) >> 6;   // head
      const int i = d >> 1;            // rope pair index
      float vals[2][2] = {{acc[mt][nt][0] + b0, acc[mt][nt][1] + b1},
                          {acc[mt][nt][2] + b0, acc[mt][nt][3] + b1}};
#pragma unroll
      for (int rr = 0; rr < 2; rr++) {
        const int m = r + rr * 8;
        const int bb = m >> 11, l = m & 2047;
        const float x1 = vals[rr][0], x2 = vals[rr][1];
        if (seg == 2) {
          __half* vp = V + ((size_t)(bb * NHEAD + h) * HDIM + d) * SEQ + l;
          vp[0] = __float2half_rn(x1);
          vp[SEQ] = __float2half_rn(x2);
        } else {
          const float2 cs = g_rope[l * 32 + i];
          float y1 = x1 * cs.x - x2 * cs.y;
          float y2 = x1 * cs.y + x2 * cs.x;
          if (seg == 0) { y1 *= QSCALE; y2 *= QSCALE; }
          const int j = (d & 15) >> 1;
          const int pd = (d & ~15) + (((j & 3) * 2 + (j >> 2)) << 1);
          __half* dp = (seg == 0 ? Q : K) +
                       ((size_t)(bb * NHEAD + h) * SEQ + l) * HDIM + pd;
          *(__half2*)dp = __floats2half2_rn(y1, y2);
        }
      }
    }
  }
}

// ---------------- fp16 tensor-core causal flash attention -------------------
// 128 q-rows per block, 8 warps, BN=64 keys/tile, 3-stage cp.async ring,
// ONE __syncthreads per tile. Softmax in base-2 (Q pre-scaled by log2e).
#define KS_H 80    // K tile row stride (halves)
#define VT_H 72    // Vt tile row stride
#define PS_H 72    // P/Q staging stride
#define KBUF_H (64 * KS_H)
#define VBUF_H (64 * VT_H)
#define PS_BUF_H (128 * PS_H)
#define FLASH_SMEM ((3 * (KBUF_H + VBUF_H) + PS_BUF_H) * 2 + 3 * 64 * 4)

__global__ __launch_bounds__(256, 2) void flash_mma_kernel(
    const __half* __restrict__ Q, const __half* __restrict__ K,
    const __half* __restrict__ V, const int* __restrict__ amask,
    __half* __restrict__ O) {
  extern __shared__ __half smh[];
  __half* Ksb = smh;                     // 3 stages
  __half* Vtb = Ksb + 3 * KBUF_H;        // 3 stages
  __half* Ps = Vtb + 3 * VBUF_H;
  int* msk = (int*)(Ps + PS_BUF_H);      // [3][64]

  const int tid = threadIdx.x;
  const int warp = tid >> 5, lane = tid & 31;
  const int g = lane >> 2, tig = lane & 3;
  const int bx = (int)(gridDim.x - 1 - blockIdx.x);  // heavy blocks first
  const int h = blockIdx.y, b = blockIdx.z;
  const int q0 = bx << 7;
  const size_t base = (size_t)(b * NHEAD + h) * SEQ * HDIM;
  const size_t vbase = (size_t)(b * NHEAD + h) * HDIM * SEQ;

  // ---- stage Q tile (128x64 halves) through Ps, hoist fragments ----
#pragma unroll
  for (int i = 0; i < 4; i++) {
    const int p = tid + (i << 8);
    const int r = p >> 3, c = (p & 7) << 3;
    *(uint4*)(Ps + r * PS_H + c) =
        *(const uint4*)(Q + base + (size_t)(q0 + r) * HDIM + c);
  }
  __syncthreads();
  uint32_t qf[4][4];
  {
    const __half* qb = Ps + (warp * 16 + g) * PS_H;
#pragma unroll
    for (int ks = 0; ks < 4; ks++) {
      const int off = ks * 16 + 4 * tig;
      uint2 q02 = *(const uint2*)(qb + off);
      uint2 q13 = *(const uint2*)(qb + 8 * PS_H + off);
      qf[ks][0] = q02.x;
      qf[ks][2] = q02.y;
      qf[ks][1] = q13.x;
      qf[ks][3] = q13.y;
    }
  }
  __syncthreads();  // Ps becomes per-warp P staging

  auto prefetch = [&](int kt, int stg) {
    const int k0 = kt << 6;
    __half* Ks_ = Ksb + stg * KBUF_H;
    __half* Vt_ = Vtb + stg * VBUF_H;
#pragma unroll
    for (int i = 0; i < 2; i++) {
      const int p = tid + (i << 8);
      const int r = p >> 3, c = (p & 7) << 3;
      uint32_t dk = (uint32_t)__cvta_generic_to_shared(Ks_ + r * KS_H + c);
      CPA16(dk, K + base + (size_t)(k0 + r) * HDIM + c);
      uint32_t dv = (uint32_t)__cvta_generic_to_shared(Vt_ + r * VT_H + c);
      CPA16(dv, V + vbase + (size_t)r * SEQ + k0 + c);
    }
    if (tid < 64) msk[stg * 64 + tid] = amask[b * SEQ + k0 + tid];
    asm volatile("cp.async.commit_group;\n");
  };

  float m0 = -1e30f, m1 = -1e30f, l0 = 0.0f, l1 = 0.0f;
  float o[8][4];
#pragma unroll
  for (int nt = 0; nt < 8; nt++)
#pragma unroll
    for (int c = 0; c < 4; c++) o[nt][c] = 0.0f;

  const int NT = (q0 >> 6) + 2;
  const int rg0 = q0 + warp * 16 + g;

  prefetch(0, 0);
  if (NT > 1) prefetch(1, 1);

  for (int kt = 0; kt < NT; kt++) {
    const int stg = kt % 3;
    if (kt < NT - 1)
      asm volatile("cp.async.wait_group 1;\n");
    else
      asm volatile("cp.async.wait_group 0;\n");
    __syncthreads();  // single barrier: tile kt visible; stage (kt+2)%3 free

    if (kt + 2 < NT) prefetch(kt + 2, (kt + 2) % 3);

    const __half* Ks_ = Ksb + stg * KBUF_H;
    const __half* Vt_ = Vtb + stg * VBUF_H;
    const int* mk = msk + stg * 64;

    // ---- S = Q @ K^T (pre-scaled by log2e/8) ----
    float s[8][4];
#pragma unroll
    for (int nt = 0; nt < 8; nt++)
#pragma unroll
      for (int c = 0; c < 4; c++) s[nt][c] = 0.0f;

#pragma unroll
    for (int ks = 0; ks < 4; ks++) {
      const int off = ks * 16 + 4 * tig;
#pragma unroll
      for (int nt = 0; nt < 8; nt++) {
        uint2 bv = *(const uint2*)(Ks_ + (nt * 8 + g) * KS_H + off);
        uint32_t bf[2] = {bv.x, bv.y};
        mma_f16(s[nt], qf[ks], bf);
      }
    }

    // ---- mask ----
    if (kt >= NT - 2) {
      const int k0 = kt << 6;
#pragma unroll
      for (int nt = 0; nt < 8; nt++) {
        const int cg = k0 + nt * 8 + 2 * tig;
        const int m_a = mk[nt * 8 + 2 * tig], m_b = mk[nt * 8 + 2 * tig + 1];
        if (!(m_a && cg <= rg0)) s[nt][0] = -1e30f;
        if (!(m_b && cg + 1 <= rg0)) s[nt][1] = -1e30f;
        if (!(m_a && cg <= rg0 + 8)) s[nt][2] = -1e30f;
        if (!(m_b && cg + 1 <= rg0 + 8)) s[nt][3] = -1e30f;
      }
    } else {
#pragma unroll
      for (int nt = 0; nt < 8; nt++) {
        const int m_a = mk[nt * 8 + 2 * tig], m_b = mk[nt * 8 + 2 * tig + 1];
        if (!m_a) { s[nt][0] = -1e30f; s[nt][2] = -1e30f; }
        if (!m_b) { s[nt][1] = -1e30f; s[nt][3] = -1e30f; }
      }
    }

    // ---- online softmax (base-2) ----
    float mx0 = -1e30f, mx1 = -1e30f;
#pragma unroll
    for (int nt = 0; nt < 8; nt++) {
      mx0 = fmaxf(mx0, fmaxf(s[nt][0], s[nt][1]));
      mx1 = fmaxf(mx1, fmaxf(s[nt][2], s[nt][3]));
    }
    mx0 = fmaxf(mx0, __shfl_xor_sync(0xffffffffu, mx0, 1));
    mx0 = fmaxf(mx0, __shfl_xor_sync(0xffffffffu, mx0, 2));
    mx1 = fmaxf(mx1, __shfl_xor_sync(0xffffffffu, mx1, 1));
    mx1 = fmaxf(mx1, __shfl_xor_sync(0xffffffffu, mx1, 2));
    const float nm0 = fmaxf(m0, mx0), nm1 = fmaxf(m1, mx1);
    const float corr0 = ex2f(m0 - nm0), corr1 = ex2f(m1 - nm1);
    m0 = nm0;
    m1 = nm1;

    float sum0 = 0.0f, sum1 = 0.0f;
#pragma unroll
    for (int nt = 0; nt < 8; nt++) {
      s[nt][0] = ex2f(s[nt][0] - nm0);
      s[nt][1] = ex2f(s[nt][1] - nm0);
      s[nt][2] = ex2f(s[nt][2] - nm1);
      s[nt][3] = ex2f(s[nt][3] - nm1);
      sum0 += s[nt][0] + s[nt][1];
      sum1 += s[nt][2] + s[nt][3];
    }
    sum0 += __shfl_xor_sync(0xffffffffu, sum0, 1);
    sum0 += __shfl_xor_sync(0xffffffffu, sum0, 2);
    sum1 += __shfl_xor_sync(0xffffffffu, sum1, 1);
    sum1 += __shfl_xor_sync(0xffffffffu, sum1, 2);
    l0 = l0 * corr0 + sum0;
    l1 = l1 * corr1 + sum1;

#pragma unroll
    for (int nt = 0; nt < 8; nt++) {
      o[nt][0] *= corr0;
      o[nt][1] *= corr0;
      o[nt][2] *= corr1;
      o[nt][3] *= corr1;
    }

    // ---- stage P as fp16 (C-layout -> A-layout) in per-warp Ps region ----
    __half* pr = Ps + (warp * 16 + g) * PS_H;
#pragma unroll
    for (int nt = 0; nt < 8; nt++) {
      const int c0 = nt * 8 + 2 * tig;
      *(__half2*)(pr + c0) = __floats2half2_rn(s[nt][0], s[nt][1]);
      *(__half2*)(pr + 8 * PS_H + c0) = __floats2half2_rn(s[nt][2], s[nt][3]);
    }
    __syncwarp();

    // ---- O += P @ V ----
    const __half* pb = Ps + (warp * 16 + g) * PS_H;
#pragma unroll
    for (int ks = 0; ks < 4; ks++) {
      const int off = ks * 16 + 2 * tig;
      uint32_t a[4];
      a[0] = *(const uint32_t*)(pb + off);
      a[1] = *(const uint32_t*)(pb + 8 * PS_H + off);
      a[2] = *(const uint32_t*)(pb + off + 8);
      a[3] = *(const uint32_t*)(pb + 8 * PS_H + off + 8);
#pragma unroll
      for (int nt = 0; nt < 8; nt++) {
        const __half* vb = Vt_ + (nt * 8 + g) * VT_H + off;
        uint32_t bf[2];
        bf[0] = *(const uint32_t*)(vb);
        bf[1] = *(const uint32_t*)(vb + 8);
        mma_f16(o[nt], a, bf);
      }
    }
    __syncwarp();
  }

  // ---- write O fp16 perm16 to [B, L, H*Dh] for the proj GEMM ----
  const float inv0 = 1.0f / l0, inv1 = 1.0f / l1;
#pragma unroll
  for (int nt = 0; nt < 8; nt++) {
    const int dl = nt * 8 + 2 * tig;
    const int j = (dl & 15) >> 1;
    const int col = h * HDIM + (dl & ~15) + (((j & 3) * 2 + (j >> 2)) << 1);
    *(__half2*)(O + (size_t)(b * SEQ + rg0) * EMBD + col) =
        __floats2half2_rn(o[nt][0] * inv0, o[nt][1] * inv0);
    *(__half2*)(O + (size_t)(b * SEQ + rg0 + 8) * EMBD + col) =
        __floats2half2_rn(o[nt][2] * inv1, o[nt][3] * inv1);
  }
}

// ---------------------------------------------------------------------------
extern "C" void kernel_launch(void* const* d_in, const int* in_sizes, int n_in,
                              void* d_out, int out_size) {
  const float* x     = (const float*)d_in[0];
  const float* Wqkv  = (const float*)d_in[1];
  const float* bqkv  = (const float*)d_in[2];
  const float* Wproj = (const float*)d_in[3];
  const float* bproj = (const float*)d_in[4];
  const int*   amask = (const int*)d_in[5];
  float* out = (float*)d_out;

  __half *q, *k, *v, *att, *xh, *wqkvT, *wprojT;
  cudaGetSymbolAddress((void**)&q, g_q);
  cudaGetSymbolAddress((void**)&k, g_k);
  cudaGetSymbolAddress((void**)&v, g_v);
  cudaGetSymbolAddress((void**)&att, g_att);
  cudaGetSymbolAddress((void**)&xh, g_xh);
  cudaGetSymbolAddress((void**)&wqkvT, g_wqkvT);
  cudaGetSymbolAddress((void**)&wprojT, g_wprojT);

  cudaFuncSetAttribute(gemm_f16_kernel,
                       cudaFuncAttributeMaxDynamicSharedMemorySize, GEMM_SMEM);
  cudaFuncSetAttribute(gemm_qkv_rope_kernel,
                       cudaFuncAttributeMaxDynamicSharedMemorySize, GEMM_SMEM);
  cudaFuncSetAttribute(flash_mma_kernel,
                       cudaFuncAttributeMaxDynamicSharedMemorySize, FLASH_SMEM);

  // 0. Operand prep (x round+perm16 + rope table; both weight transposes)
  round_permute_rope<<<1184, 256>>>(x, xh, TOKENS * EMBD / 16);
  {
    dim3 gt(96 + 32, EMBD / 32);
    transpose_both_kernel<<<gt, dim3(32, 8)>>>(Wqkv, wqkvT, Wproj, wprojT);
  }

  // 1. QKV projection + fused RoPE/split -> q (*log2e/8), k, v
  dim3 g1(QKVDIM / 128, TOKENS / 128);
  gemm_qkv_rope_kernel<<<g1, 256, GEMM_SMEM>>>(xh, wqkvT, bqkv, q, k, v);

  // 2. Causal flash attention (fp16 tensor cores) -> att (fp16, perm16)
  dim3 g3(SEQ / 128, NHEAD, BATCH);
  flash_mma_kernel<<<g3, 256, FLASH_SMEM>>>(q, k, v, amask, att);

  // 3. Output projection -> fp32 out
  dim3 g4(EMBD / 128, TOKENS / 128);
  gemm_f16_kernel<<<g4, 256, GEMM_SMEM>>>(att, wprojT, bproj, out, EMBD, EMBD);
}

// round 13
// speedup vs baseline: 1.1373x; 1.0246x over previous
#include <cuda_runtime.h>
#include <cuda_fp16.h>
#include <math.h>
#include <cstdint>

// Problem constants: B=4, L=2048, D=1024, H=16, Dh=64, 3D=3072
#define BATCH   4
#define SEQ     2048
#define EMBD    1024
#define NHEAD   16
#define HDIM    64
#define TOKENS  (BATCH * SEQ)            // 8192
#define QKVDIM  (3 * EMBD)               // 3072

// ---------------- scratch (static __device__, no allocation) ----------------
__device__ __half g_q[(size_t)BATCH * NHEAD * SEQ * HDIM];  // /8*log2e, perm16
__device__ __half g_k[(size_t)BATCH * NHEAD * SEQ * HDIM];  // perm16
__device__ __half g_v[(size_t)BATCH * NHEAD * HDIM * SEQ];  // [B,H,Dh,L]
__device__ __half g_att[(size_t)TOKENS * EMBD];             // [B,L,D] perm16
__device__ float2 g_rope[(size_t)SEQ * 32];                 // cos/sin table
__device__ __half g_xh[(size_t)TOKENS * EMBD];              // x fp16, perm16
__device__ __half g_wqkvT[(size_t)QKVDIM * EMBD];           // W_qkv^T fp16, perm16
__device__ __half g_wprojT[(size_t)EMBD * EMBD];            // W_proj^T fp16, perm16

// ---------------- helpers ---------------------------------------------------
__device__ __forceinline__ void mma_f16(float* d, const uint32_t* a,
                                        const uint32_t* b) {
  asm volatile(
      "mma.sync.aligned.m16n8k16.row.col.f32.f16.f16.f32 "
      "{%0,%1,%2,%3},{%4,%5,%6,%7},{%8,%9},{%0,%1,%2,%3};"
      : "+f"(d[0]), "+f"(d[1]), "+f"(d[2]), "+f"(d[3])
      : "r"(a[0]), "r"(a[1]), "r"(a[2]), "r"(a[3]), "r"(b[0]), "r"(b[1]));
}

#define CPA16(dst, src) \
  asm volatile("cp.async.cg.shared.global [%0], [%1], 16;\n" ::"r"(dst), "l"(src))

__device__ __forceinline__ float ex2f(float x) {
  float y;
  asm("ex2.approx.f32 %0, %1;" : "=f"(y) : "f"(x));
  return y;
}
__device__ __forceinline__ uint32_t h2ex2(uint32_t x) {
  uint32_t y;
  asm("ex2.approx.f16x2 %0, %1;" : "=r"(y) : "r"(x));
  return y;
}

// 16-group permutation: pair j (0..7) goes to pair position (j&3)*2 + (j>>2).
__device__ __host__ __forceinline__ int perm16(int k) {
  const int j = (k & 15) >> 1;
  return (k & ~15) + (((j & 3) * 2 + (j >> 2)) << 1) + (k & 1);
}

#define QSCALE (0.125f * 1.44269504f)   // 1/sqrt(64) * log2(e)

// ------------- fp16 round + perm16 (x) + RoPE table fill --------------------
__global__ __launch_bounds__(256) void round_permute_rope(
    const float* __restrict__ in, __half* __restrict__ out, int n16) {
  if (blockIdx.x < 256) {
    const int idx = blockIdx.x * 256 + threadIdx.x;
    const int l = idx >> 5, i = idx & 31;
    const float inv_freq = 1.0f / powf(10000.0f, (2.0f * (float)i) / 64.0f);
    float s, c;
    sincosf((float)l * inv_freq, &s, &c);
    g_rope[idx] = make_float2(c, s);
  }
  int i = blockIdx.x * 256 + threadIdx.x;
  const int stride = gridDim.x * 256;
  for (; i < n16; i += stride) {
    const float4* ip = (const float4*)(in + 16 * (size_t)i);
    float v[16];
    *(float4*)(v + 0) = ip[0];
    *(float4*)(v + 4) = ip[1];
    *(float4*)(v + 8) = ip[2];
    *(float4*)(v + 12) = ip[3];
    __half h[16];
#pragma unroll
    for (int j = 0; j < 8; j++) {
      const int pp = (j & 3) * 2 + (j >> 2);
      h[pp * 2] = __float2half_rn(v[2 * j]);
      h[pp * 2 + 1] = __float2half_rn(v[2 * j + 1]);
    }
    uint4* op = (uint4*)(out + 16 * (size_t)i);
    op[0] = *(uint4*)(h);
    op[1] = *(uint4*)(h + 8);
  }
}

// ------------- both weight transposes in ONE launch -------------------------
__global__ __launch_bounds__(256) void transpose_both_kernel(
    const float* __restrict__ Wqkv, __half* __restrict__ outQkv,
    const float* __restrict__ Wproj, __half* __restrict__ outProj) {
  __shared__ float tile[32][33];
  const float* in;
  __half* out;
  int N, bxx;
  if (blockIdx.x < 96) {
    in = Wqkv; out = outQkv; N = QKVDIM; bxx = blockIdx.x;
  } else {
    in = Wproj; out = outProj; N = EMBD; bxx = blockIdx.x - 96;
  }
  const int K = EMBD;
  const int k0 = blockIdx.y * 32, n0 = bxx * 32;
  const int tx = threadIdx.x, ty = threadIdx.y;  // 32 x 8
#pragma unroll
  for (int i = 0; i < 32; i += 8)
    tile[ty + i][tx] = in[(size_t)(k0 + ty + i) * N + n0 + tx];
  __syncthreads();
  const int pk = perm16(tx);
#pragma unroll
  for (int i = 0; i < 32; i += 8) {
    const int n = ty + i;
    out[(size_t)(n0 + n) * K + k0 + pk] = __float2half_rn(tile[tx][n]);
  }
}

// ---------------- GEMM core (fp16 operands, fp32 accum) ---------------------
#define ABS_H 80                        // smem row stride in halves (160B)
#define AB_BUF_H (128 * ABS_H)          // 10240 halves
#define GEMM_SMEM (4 * AB_BUF_H * 2)    // 81920 B

__device__ __forceinline__ void gemm_tile_compute(
    const __half* __restrict__ A, const __half* __restrict__ BT, __half* sm,
    int m0, int n0, int K, float acc[4][4][4]) {
  const int tid = threadIdx.x;
  const int warp = tid >> 5, lane = tid & 31;
  const int wm = warp >> 2, wn = warp & 3;
  const int g = lane >> 2, tig = lane & 3;

#pragma unroll
  for (int i = 0; i < 4; i++)
#pragma unroll
    for (int j = 0; j < 4; j++)
#pragma unroll
      for (int t = 0; t < 4; t++) acc[i][j][t] = 0.0f;

  auto prefetch = [&](int kt, int buf) {
    __half* As = sm + buf * AB_BUF_H;
    __half* Bs = sm + 2 * AB_BUF_H + buf * AB_BUF_H;
    const int k0 = kt << 6;
#pragma unroll
    for (int j = 0; j < 4; j++) {
      const int p = tid + (j << 8);
      const int r = p >> 3, c = (p & 7) << 3;
      uint32_t da = (uint32_t)__cvta_generic_to_shared(As + r * ABS_H + c);
      CPA16(da, A + (size_t)(m0 + r) * K + k0 + c);
      uint32_t db = (uint32_t)__cvta_generic_to_shared(Bs + r * ABS_H + c);
      CPA16(db, BT + (size_t)(n0 + r) * K + k0 + c);
    }
    asm volatile("cp.async.commit_group;\n");
  };

  const int NT = K >> 6;
  prefetch(0, 0);

  for (int kt = 0; kt < NT; kt++) {
    const int buf = kt & 1;
    if (kt + 1 < NT) {
      prefetch(kt + 1, buf ^ 1);
      asm volatile("cp.async.wait_group 1;\n");
    } else {
      asm volatile("cp.async.wait_group 0;\n");
    }
    __syncthreads();

    const __half* As = sm + buf * AB_BUF_H;
    const __half* Bs = sm + 2 * AB_BUF_H + buf * AB_BUF_H;

#pragma unroll
    for (int ks = 0; ks < 4; ks++) {
      const int koff = ks * 16 + 4 * tig;
      uint32_t af[4][4], bf[4][2];
#pragma unroll
      for (int mt = 0; mt < 4; mt++) {
        const int row = wm * 64 + mt * 16 + g;
        uint2 a02 = *(const uint2*)(As + row * ABS_H + koff);
        uint2 a13 = *(const uint2*)(As + (row + 8) * ABS_H + koff);
        af[mt][0] = a02.x;
        af[mt][2] = a02.y;
        af[mt][1] = a13.x;
        af[mt][3] = a13.y;
      }
#pragma unroll
      for (int nt = 0; nt < 4; nt++) {
        const int nrow = wn * 32 + nt * 8 + g;
        uint2 b01 = *(const uint2*)(Bs + nrow * ABS_H + koff);
        bf[nt][0] = b01.x;
        bf[nt][1] = b01.y;
      }
#pragma unroll
      for (int mt = 0; mt < 4; mt++)
#pragma unroll
        for (int nt = 0; nt < 4; nt++) mma_f16(acc[mt][nt], af[mt], bf[nt]);
    }
    __syncthreads();
  }
}

// ---------------- plain GEMM + bias (proj, fp32 out) ------------------------
__global__ __launch_bounds__(256) void gemm_f16_kernel(
    const __half* __restrict__ A, const __half* __restrict__ BT,
    const float* __restrict__ bias, float* __restrict__ C, int N, int K) {
  extern __shared__ __half smh[];
  const int tid = threadIdx.x;
  const int warp = tid >> 5, lane = tid & 31;
  const int wm = warp >> 2, wn = warp & 3;
  const int g = lane >> 2, tig = lane & 3;
  const int m0 = blockIdx.y << 7, n0 = blockIdx.x << 7;

  float acc[4][4][4];
  gemm_tile_compute(A, BT, smh, m0, n0, K, acc);

#pragma unroll
  for (int mt = 0; mt < 4; mt++) {
    const int r = m0 + wm * 64 + mt * 16 + g;
#pragma unroll
    for (int nt = 0; nt < 4; nt++) {
      const int c = n0 + wn * 32 + nt * 8 + 2 * tig;
      const float b0 = __ldg(bias + c), b1 = __ldg(bias + c + 1);
      float2 v0 = {acc[mt][nt][0] + b0, acc[mt][nt][1] + b1};
      float2 v1 = {acc[mt][nt][2] + b0, acc[mt][nt][3] + b1};
      *(float2*)(C + (size_t)r * N + c) = v0;
      *(float2*)(C + (size_t)(r + 8) * N + c) = v1;
    }
  }
}

// ---------------- QKV GEMM with fused RoPE/split epilogue -------------------
__global__ __launch_bounds__(256) void gemm_qkv_rope_kernel(
    const __half* __restrict__ A, const __half* __restrict__ BT,
    const float* __restrict__ bias, __half* __restrict__ Q,
    __half* __restrict__ K, __half* __restrict__ V) {
  extern __shared__ __half smh[];
  const int tid = threadIdx.x;
  const int warp = tid >> 5, lane = tid & 31;
  const int wm = warp >> 2, wn = warp & 3;
  const int g = lane >> 2, tig = lane & 3;
  const int m0 = blockIdx.y << 7, n0 = blockIdx.x << 7;

  float acc[4][4][4];
  gemm_tile_compute(A, BT, smh, m0, n0, EMBD, acc);

  const int seg = n0 >> 10;  // 0=q, 1=k, 2=v (block-uniform)

#pragma unroll
  for (int mt = 0; mt < 4; mt++) {
    const int r = m0 + wm * 64 + mt * 16 + g;
#pragma unroll
    for (int nt = 0; nt < 4; nt++) {
      const int c = n0 + wn * 32 + nt * 8 + 2 * tig;  // even column
      const float b0 = __ldg(bias + c), b1 = __ldg(bias + c + 1);
      const int d = c & 63;
      const int h = (c & 1023) >> 6;
      const int i = d >> 1;
      float vals[2][2] = {{acc[mt][nt][0] + b0, acc[mt][nt][1] + b1},
                          {acc[mt][nt][2] + b0, acc[mt][nt][3] + b1}};
#pragma unroll
      for (int rr = 0; rr < 2; rr++) {
        const int m = r + rr * 8;
        const int bb = m >> 11, l = m & 2047;
        const float x1 = vals[rr][0], x2 = vals[rr][1];
        if (seg == 2) {
          __half* vp = V + ((size_t)(bb * NHEAD + h) * HDIM + d) * SEQ + l;
          vp[0] = __float2half_rn(x1);
          vp[SEQ] = __float2half_rn(x2);
        } else {
          const float2 cs = g_rope[l * 32 + i];
          float y1 = x1 * cs.x - x2 * cs.y;
          float y2 = x1 * cs.y + x2 * cs.x;
          if (seg == 0) { y1 *= QSCALE; y2 *= QSCALE; }
          const int j = (d & 15) >> 1;
          const int pd = (d & ~15) + (((j & 3) * 2 + (j >> 2)) << 1);
          __half* dp = (seg == 0 ? Q : K) +
                       ((size_t)(bb * NHEAD + h) * SEQ + l) * HDIM + pd;
          *(__half2*)dp = __floats2half2_rn(y1, y2);
        }
      }
    }
  }
}

// ---------------- fp16 tensor-core causal flash attention -------------------
// 128 q-rows per block, 8 warps, BN=64 keys/tile, 3-stage cp.async ring.
// Softmax base-2 with f16x2 ex2; row-sums l via extra all-ones V column.
#define KS_H 80    // K tile row stride (halves)
#define VT_H 72    // Vt tile row stride
#define PS_H 72    // P/Q staging stride
#define KBUF_H (64 * KS_H)
#define VBUF_H (72 * VT_H)   // rows 0..63 data, 64 = ones, 65..71 zero
#define PS_BUF_H (128 * PS_H)
#define FLASH_SMEM ((3 * (KBUF_H + VBUF_H) + PS_BUF_H) * 2 + 3 * 64 * 4)

__global__ __launch_bounds__(256, 2) void flash_mma_kernel(
    const __half* __restrict__ Q, const __half* __restrict__ K,
    const __half* __restrict__ V, const int* __restrict__ amask,
    __half* __restrict__ O) {
  extern __shared__ __half smh[];
  __half* Ksb = smh;                     // 3 stages
  __half* Vtb = Ksb + 3 * KBUF_H;        // 3 stages
  __half* Ps = Vtb + 3 * VBUF_H;
  int* msk = (int*)(Ps + PS_BUF_H);      // [3][64]

  const int tid = threadIdx.x;
  const int warp = tid >> 5, lane = tid & 31;
  const int g = lane >> 2, tig = lane & 3;
  const int bx = (int)(gridDim.x - 1 - blockIdx.x);  // heavy blocks first
  const int h = blockIdx.y, b = blockIdx.z;
  const int q0 = bx << 7;
  const size_t base = (size_t)(b * NHEAD + h) * SEQ * HDIM;
  const size_t vbase = (size_t)(b * NHEAD + h) * HDIM * SEQ;

  // ---- ones/zero rows 64..71 of each V stage (row 64 = 1.0, rest 0) ----
  for (int idx = tid; idx < 3 * 8 * VT_H; idx += 256) {
    const int stg = idx / (8 * VT_H);
    const int rem = idx % (8 * VT_H);
    const int row = 64 + rem / VT_H;
    Vtb[stg * VBUF_H + row * VT_H + (rem % VT_H)] =
        (row == 64) ? __float2half(1.0f) : __float2half(0.0f);
  }

  // ---- stage Q tile (128x64 halves) through Ps, hoist fragments ----
#pragma unroll
  for (int i = 0; i < 4; i++) {
    const int p = tid + (i << 8);
    const int r = p >> 3, c = (p & 7) << 3;
    *(uint4*)(Ps + r * PS_H + c) =
        *(const uint4*)(Q + base + (size_t)(q0 + r) * HDIM + c);
  }
  __syncthreads();
  uint32_t qf[4][4];
  {
    const __half* qb = Ps + (warp * 16 + g) * PS_H;
#pragma unroll
    for (int ks = 0; ks < 4; ks++) {
      const int off = ks * 16 + 4 * tig;
      uint2 q02 = *(const uint2*)(qb + off);
      uint2 q13 = *(const uint2*)(qb + 8 * PS_H + off);
      qf[ks][0] = q02.x;
      qf[ks][2] = q02.y;
      qf[ks][1] = q13.x;
      qf[ks][3] = q13.y;
    }
  }
  __syncthreads();  // Ps becomes per-warp P staging

  auto prefetch = [&](int kt, int stg) {
    const int k0 = kt << 6;
    __half* Ks_ = Ksb + stg * KBUF_H;
    __half* Vt_ = Vtb + stg * VBUF_H;
#pragma unroll
    for (int i = 0; i < 2; i++) {
      const int p = tid + (i << 8);
      const int r = p >> 3, c = (p & 7) << 3;
      uint32_t dk = (uint32_t)__cvta_generic_to_shared(Ks_ + r * KS_H + c);
      CPA16(dk, K + base + (size_t)(k0 + r) * HDIM + c);
      uint32_t dv = (uint32_t)__cvta_generic_to_shared(Vt_ + r * VT_H + c);
      CPA16(dv, V + vbase + (size_t)r * SEQ + k0 + c);
    }
    if (tid < 64) msk[stg * 64 + tid] = amask[b * SEQ + k0 + tid];
    asm volatile("cp.async.commit_group;\n");
  };

  float m0 = -1e30f, m1 = -1e30f;
  float o[9][4];   // o[8] column 64 = running row-sum l (via ones column)
#pragma unroll
  for (int nt = 0; nt < 9; nt++)
#pragma unroll
    for (int c = 0; c < 4; c++) o[nt][c] = 0.0f;

  const int NT = (q0 >> 6) + 2;
  const int rg0 = q0 + warp * 16 + g;

  prefetch(0, 0);
  if (NT > 1) prefetch(1, 1);

  for (int kt = 0; kt < NT; kt++) {
    const int stg = kt % 3;
    if (kt < NT - 1)
      asm volatile("cp.async.wait_group 1;\n");
    else
      asm volatile("cp.async.wait_group 0;\n");
    __syncthreads();  // single barrier: tile kt visible; stage (kt+2)%3 free

    if (kt + 2 < NT) prefetch(kt + 2, (kt + 2) % 3);

    const __half* Ks_ = Ksb + stg * KBUF_H;
    const __half* Vt_ = Vtb + stg * VBUF_H;
    const int* mk = msk + stg * 64;

    // ---- S = Q @ K^T (pre-scaled by log2e/8) ----
    float s[8][4];
#pragma unroll
    for (int nt = 0; nt < 8; nt++)
#pragma unroll
      for (int c = 0; c < 4; c++) s[nt][c] = 0.0f;

#pragma unroll
    for (int ks = 0; ks < 4; ks++) {
      const int off = ks * 16 + 4 * tig;
#pragma unroll
      for (int nt = 0; nt < 8; nt++) {
        uint2 bv = *(const uint2*)(Ks_ + (nt * 8 + g) * KS_H + off);
        uint32_t bf[2] = {bv.x, bv.y};
        mma_f16(s[nt], qf[ks], bf);
      }
    }

    // ---- mask ----
    if (kt >= NT - 2) {
      const int k0 = kt << 6;
#pragma unroll
      for (int nt = 0; nt < 8; nt++) {
        const int cg = k0 + nt * 8 + 2 * tig;
        const int m_a = mk[nt * 8 + 2 * tig], m_b = mk[nt * 8 + 2 * tig + 1];
        if (!(m_a && cg <= rg0)) s[nt][0] = -1e30f;
        if (!(m_b && cg + 1 <= rg0)) s[nt][1] = -1e30f;
        if (!(m_a && cg <= rg0 + 8)) s[nt][2] = -1e30f;
        if (!(m_b && cg + 1 <= rg0 + 8)) s[nt][3] = -1e30f;
      }
    } else {
#pragma unroll
      for (int nt = 0; nt < 8; nt++) {
        const int m_a = mk[nt * 8 + 2 * tig], m_b = mk[nt * 8 + 2 * tig + 1];
        if (!m_a) { s[nt][0] = -1e30f; s[nt][2] = -1e30f; }
        if (!m_b) { s[nt][1] = -1e30f; s[nt][3] = -1e30f; }
      }
    }

    // ---- online softmax (base-2): max, corr, P via f16x2 ex2 ----
    float mx0 = -1e30f, mx1 = -1e30f;
#pragma unroll
    for (int nt = 0; nt < 8; nt++) {
      mx0 = fmaxf(mx0, fmaxf(s[nt][0], s[nt][1]));
      mx1 = fmaxf(mx1, fmaxf(s[nt][2], s[nt][3]));
    }
    mx0 = fmaxf(mx0, __shfl_xor_sync(0xffffffffu, mx0, 1));
    mx0 = fmaxf(mx0, __shfl_xor_sync(0xffffffffu, mx0, 2));
    mx1 = fmaxf(mx1, __shfl_xor_sync(0xffffffffu, mx1, 1));
    mx1 = fmaxf(mx1, __shfl_xor_sync(0xffffffffu, mx1, 2));
    const float nm0 = fmaxf(m0, mx0), nm1 = fmaxf(m1, mx1);
    const float corr0 = ex2f(m0 - nm0), corr1 = ex2f(m1 - nm1);
    m0 = nm0;
    m1 = nm1;

#pragma unroll
    for (int nt = 0; nt < 9; nt++) {
      o[nt][0] *= corr0;
      o[nt][1] *= corr0;
      o[nt][2] *= corr1;
      o[nt][3] *= corr1;
    }

    // ---- P = 2^(s-nm) as fp16 pairs, staged in per-warp Ps region ----
    __half* pr = Ps + (warp * 16 + g) * PS_H;
#pragma unroll
    for (int nt = 0; nt < 8; nt++) {
      const int c0 = nt * 8 + 2 * tig;
      __half2 d01 = __floats2half2_rn(s[nt][0] - nm0, s[nt][1] - nm0);
      __half2 d23 = __floats2half2_rn(s[nt][2] - nm1, s[nt][3] - nm1);
      *(uint32_t*)(pr + c0) = h2ex2(*(uint32_t*)&d01);
      *(uint32_t*)(pr + 8 * PS_H + c0) = h2ex2(*(uint32_t*)&d23);
    }
    __syncwarp();

    // ---- O += P @ [V | ones] (nt=8 column accumulates row-sum l) ----
    const __half* pb = Ps + (warp * 16 + g) * PS_H;
#pragma unroll
    for (int ks = 0; ks < 4; ks++) {
      const int off = ks * 16 + 2 * tig;
      uint32_t a[4];
      a[0] = *(const uint32_t*)(pb + off);
      a[1] = *(const uint32_t*)(pb + 8 * PS_H + off);
      a[2] = *(const uint32_t*)(pb + off + 8);
      a[3] = *(const uint32_t*)(pb + 8 * PS_H + off + 8);
#pragma unroll
      for (int nt = 0; nt < 9; nt++) {
        const __half* vb = Vt_ + (nt * 8 + g) * VT_H + off;
        uint32_t bf[2];
        bf[0] = *(const uint32_t*)(vb);
        bf[1] = *(const uint32_t*)(vb + 8);
        mma_f16(o[nt], a, bf);
      }
    }
    __syncwarp();
  }

  // ---- l lives in o[8] col 64 (lane tig=0 of each quad); broadcast ----
  const float l0 = __shfl_sync(0xffffffffu, o[8][0], lane & ~3);
  const float l1 = __shfl_sync(0xffffffffu, o[8][2], lane & ~3);
  const float inv0 = 1.0f / l0, inv1 = 1.0f / l1;

  // ---- write O fp16 perm16 to [B, L, H*Dh] for the proj GEMM ----
#pragma unroll
  for (int nt = 0; nt < 8; nt++) {
    const int dl = nt * 8 + 2 * tig;
    const int j = (dl & 15) >> 1;
    const int col = h * HDIM + (dl & ~15) + (((j & 3) * 2 + (j >> 2)) << 1);
    *(__half2*)(O + (size_t)(b * SEQ + rg0) * EMBD + col) =
        __floats2half2_rn(o[nt][0] * inv0, o[nt][1] * inv0);
    *(__half2*)(O + (size_t)(b * SEQ + rg0 + 8) * EMBD + col) =
        __floats2half2_rn(o[nt][2] * inv1, o[nt][3] * inv1);
  }
}

// ---------------------------------------------------------------------------
extern "C" void kernel_launch(void* const* d_in, const int* in_sizes, int n_in,
                              void* d_out, int out_size) {
  const float* x     = (const float*)d_in[0];
  const float* Wqkv  = (const float*)d_in[1];
  const float* bqkv  = (const float*)d_in[2];
  const float* Wproj = (const float*)d_in[3];
  const float* bproj = (const float*)d_in[4];
  const int*   amask = (const int*)d_in[5];
  float* out = (float*)d_out;

  __half *q, *k, *v, *att, *xh, *wqkvT, *wprojT;
  cudaGetSymbolAddress((void**)&q, g_q);
  cudaGetSymbolAddress((void**)&k, g_k);
  cudaGetSymbolAddress((void**)&v, g_v);
  cudaGetSymbolAddress((void**)&att, g_att);
  cudaGetSymbolAddress((void**)&xh, g_xh);
  cudaGetSymbolAddress((void**)&wqkvT, g_wqkvT);
  cudaGetSymbolAddress((void**)&wprojT, g_wprojT);

  cudaFuncSetAttribute(gemm_f16_kernel,
                       cudaFuncAttributeMaxDynamicSharedMemorySize, GEMM_SMEM);
  cudaFuncSetAttribute(gemm_qkv_rope_kernel,
                       cudaFuncAttributeMaxDynamicSharedMemorySize, GEMM_SMEM);
  cudaFuncSetAttribute(flash_mma_kernel,
                       cudaFuncAttributeMaxDynamicSharedMemorySize, FLASH_SMEM);

  // 0. Operand prep (x round+perm16 + rope table; both weight transposes)
  round_permute_rope<<<1184, 256>>>(x, xh, TOKENS * EMBD / 16);
  {
    dim3 gt(96 + 32, EMBD / 32);
    transpose_both_kernel<<<gt, dim3(32, 8)>>>(Wqkv, wqkvT, Wproj, wprojT);
  }

  // 1. QKV projection + fused RoPE/split -> q (*log2e/8), k, v
  dim3 g1(QKVDIM / 128, TOKENS / 128);
  gemm_qkv_rope_kernel<<<g1, 256, GEMM_SMEM>>>(xh, wqkvT, bqkv, q, k, v);

  // 2. Causal flash attention (fp16 tensor cores) -> att (fp16, perm16)
  dim3 g3(SEQ / 128, NHEAD, BATCH);
  flash_mma_kernel<<<g3, 256, FLASH_SMEM>>>(q, k, v, amask, att);

  // 3. Output projection -> fp32 out
  dim3 g4(EMBD / 128, TOKENS / 128);
  gemm_f16_kernel<<<g4, 256, GEMM_SMEM>>>(att, wprojT, bproj, out, EMBD, EMBD);
}

// round 14
// speedup vs baseline: 1.1657x; 1.0250x over previous
#include <cuda_runtime.h>
#include <cuda_fp16.h>
#include <math.h>
#include <cstdint>

// Problem constants: B=4, L=2048, D=1024, H=16, Dh=64, 3D=3072
#define BATCH   4
#define SEQ     2048
#define EMBD    1024
#define NHEAD   16
#define HDIM    64
#define TOKENS  (BATCH * SEQ)            // 8192
#define QKVDIM  (3 * EMBD)               // 3072

// ---------------- scratch (static __device__, no allocation) ----------------
__device__ __half g_q[(size_t)BATCH * NHEAD * SEQ * HDIM];  // /8*log2e, perm16
__device__ __half g_k[(size_t)BATCH * NHEAD * SEQ * HDIM];  // perm16
__device__ __half g_v[(size_t)BATCH * NHEAD * HDIM * SEQ];  // [B,H,Dh,L] L-perm16
__device__ __half g_att[(size_t)TOKENS * EMBD];             // [B,L,D] perm16
__device__ float2 g_rope[(size_t)SEQ * 32];                 // cos/sin table
__device__ __half g_xh[(size_t)TOKENS * EMBD];              // x fp16, perm16
__device__ __half g_wqkvT[(size_t)QKVDIM * EMBD];           // W_qkv^T fp16, perm16
__device__ __half g_wprojT[(size_t)EMBD * EMBD];            // W_proj^T fp16, perm16

// ---------------- helpers ---------------------------------------------------
__device__ __forceinline__ void mma_f16(float* d, const uint32_t* a,
                                        const uint32_t* b) {
  asm volatile(
      "mma.sync.aligned.m16n8k16.row.col.f32.f16.f16.f32 "
      "{%0,%1,%2,%3},{%4,%5,%6,%7},{%8,%9},{%0,%1,%2,%3};"
      : "+f"(d[0]), "+f"(d[1]), "+f"(d[2]), "+f"(d[3])
      : "r"(a[0]), "r"(a[1]), "r"(a[2]), "r"(a[3]), "r"(b[0]), "r"(b[1]));
}

#define CPA16(dst, src) \
  asm volatile("cp.async.cg.shared.global [%0], [%1], 16;\n" ::"r"(dst), "l"(src))

__device__ __forceinline__ float ex2f(float x) {
  float y;
  asm("ex2.approx.f32 %0, %1;" : "=f"(y) : "f"(x));
  return y;
}
__device__ __forceinline__ uint32_t h2ex2(uint32_t x) {
  uint32_t y;
  asm("ex2.approx.f16x2 %0, %1;" : "=r"(y) : "r"(x));
  return y;
}

// 16-group permutation: pair j (0..7) goes to pair position (j&3)*2 + (j>>2).
__device__ __host__ __forceinline__ int perm16(int k) {
  const int j = (k & 15) >> 1;
  return (k & ~15) + (((j & 3) * 2 + (j >> 2)) << 1) + (k & 1);
}

#define QSCALE (0.125f * 1.44269504f)   // 1/sqrt(64) * log2(e)

// ------------- fp16 round + perm16 (x) + RoPE table fill --------------------
__global__ __launch_bounds__(256) void round_permute_rope(
    const float* __restrict__ in, __half* __restrict__ out, int n16) {
  if (blockIdx.x < 256) {
    const int idx = blockIdx.x * 256 + threadIdx.x;
    const int l = idx >> 5, i = idx & 31;
    const float inv_freq = 1.0f / powf(10000.0f, (2.0f * (float)i) / 64.0f);
    float s, c;
    sincosf((float)l * inv_freq, &s, &c);
    g_rope[idx] = make_float2(c, s);
  }
  int i = blockIdx.x * 256 + threadIdx.x;
  const int stride = gridDim.x * 256;
  for (; i < n16; i += stride) {
    const float4* ip = (const float4*)(in + 16 * (size_t)i);
    float v[16];
    *(float4*)(v + 0) = ip[0];
    *(float4*)(v + 4) = ip[1];
    *(float4*)(v + 8) = ip[2];
    *(float4*)(v + 12) = ip[3];
    __half h[16];
#pragma unroll
    for (int j = 0; j < 8; j++) {
      const int pp = (j & 3) * 2 + (j >> 2);
      h[pp * 2] = __float2half_rn(v[2 * j]);
      h[pp * 2 + 1] = __float2half_rn(v[2 * j + 1]);
    }
    uint4* op = (uint4*)(out + 16 * (size_t)i);
    op[0] = *(uint4*)(h);
    op[1] = *(uint4*)(h + 8);
  }
}

// ------------- both weight transposes in ONE launch -------------------------
__global__ __launch_bounds__(256) void transpose_both_kernel(
    const float* __restrict__ Wqkv, __half* __restrict__ outQkv,
    const float* __restrict__ Wproj, __half* __restrict__ outProj) {
  __shared__ float tile[32][33];
  const float* in;
  __half* out;
  int N, bxx;
  if (blockIdx.x < 96) {
    in = Wqkv; out = outQkv; N = QKVDIM; bxx = blockIdx.x;
  } else {
    in = Wproj; out = outProj; N = EMBD; bxx = blockIdx.x - 96;
  }
  const int K = EMBD;
  const int k0 = blockIdx.y * 32, n0 = bxx * 32;
  const int tx = threadIdx.x, ty = threadIdx.y;  // 32 x 8
#pragma unroll
  for (int i = 0; i < 32; i += 8)
    tile[ty + i][tx] = in[(size_t)(k0 + ty + i) * N + n0 + tx];
  __syncthreads();
  const int pk = perm16(tx);
#pragma unroll
  for (int i = 0; i < 32; i += 8) {
    const int n = ty + i;
    out[(size_t)(n0 + n) * K + k0 + pk] = __float2half_rn(tile[tx][n]);
  }
}

// ---------------- GEMM core (fp16 operands, fp32 accum) ---------------------
#define ABS_H 80                        // smem row stride in halves (160B)
#define AB_BUF_H (128 * ABS_H)          // 10240 halves
#define GEMM_SMEM (4 * AB_BUF_H * 2)    // 81920 B

__device__ __forceinline__ void gemm_tile_compute(
    const __half* __restrict__ A, const __half* __restrict__ BT, __half* sm,
    int m0, int n0, int K, float acc[4][4][4]) {
  const int tid = threadIdx.x;
  const int warp = tid >> 5, lane = tid & 31;
  const int wm = warp >> 2, wn = warp & 3;
  const int g = lane >> 2, tig = lane & 3;

#pragma unroll
  for (int i = 0; i < 4; i++)
#pragma unroll
    for (int j = 0; j < 4; j++)
#pragma unroll
      for (int t = 0; t < 4; t++) acc[i][j][t] = 0.0f;

  auto prefetch = [&](int kt, int buf) {
    __half* As = sm + buf * AB_BUF_H;
    __half* Bs = sm + 2 * AB_BUF_H + buf * AB_BUF_H;
    const int k0 = kt << 6;
#pragma unroll
    for (int j = 0; j < 4; j++) {
      const int p = tid + (j << 8);
      const int r = p >> 3, c = (p & 7) << 3;
      uint32_t da = (uint32_t)__cvta_generic_to_shared(As + r * ABS_H + c);
      CPA16(da, A + (size_t)(m0 + r) * K + k0 + c);
      uint32_t db = (uint32_t)__cvta_generic_to_shared(Bs + r * ABS_H + c);
      CPA16(db, BT + (size_t)(n0 + r) * K + k0 + c);
    }
    asm volatile("cp.async.commit_group;\n");
  };

  const int NT = K >> 6;
  prefetch(0, 0);

  for (int kt = 0; kt < NT; kt++) {
    const int buf = kt & 1;
    if (kt + 1 < NT) {
      prefetch(kt + 1, buf ^ 1);
      asm volatile("cp.async.wait_group 1;\n");
    } else {
      asm volatile("cp.async.wait_group 0;\n");
    }
    __syncthreads();

    const __half* As = sm + buf * AB_BUF_H;
    const __half* Bs = sm + 2 * AB_BUF_H + buf * AB_BUF_H;

#pragma unroll
    for (int ks = 0; ks < 4; ks++) {
      const int koff = ks * 16 + 4 * tig;
      uint32_t af[4][4], bf[4][2];
#pragma unroll
      for (int mt = 0; mt < 4; mt++) {
        const int row = wm * 64 + mt * 16 + g;
        uint2 a02 = *(const uint2*)(As + row * ABS_H + koff);
        uint2 a13 = *(const uint2*)(As + (row + 8) * ABS_H + koff);
        af[mt][0] = a02.x;
        af[mt][2] = a02.y;
        af[mt][1] = a13.x;
        af[mt][3] = a13.y;
      }
#pragma unroll
      for (int nt = 0; nt < 4; nt++) {
        const int nrow = wn * 32 + nt * 8 + g;
        uint2 b01 = *(const uint2*)(Bs + nrow * ABS_H + koff);
        bf[nt][0] = b01.x;
        bf[nt][1] = b01.y;
      }
#pragma unroll
      for (int mt = 0; mt < 4; mt++)
#pragma unroll
        for (int nt = 0; nt < 4; nt++) mma_f16(acc[mt][nt], af[mt], bf[nt]);
    }
    __syncthreads();
  }
}

// ---------------- plain GEMM + bias (proj, fp32 out) ------------------------
__global__ __launch_bounds__(256) void gemm_f16_kernel(
    const __half* __restrict__ A, const __half* __restrict__ BT,
    const float* __restrict__ bias, float* __restrict__ C, int N, int K) {
  extern __shared__ __half smh[];
  const int tid = threadIdx.x;
  const int warp = tid >> 5, lane = tid & 31;
  const int wm = warp >> 2, wn = warp & 3;
  const int g = lane >> 2, tig = lane & 3;
  const int m0 = blockIdx.y << 7, n0 = blockIdx.x << 7;

  float acc[4][4][4];
  gemm_tile_compute(A, BT, smh, m0, n0, K, acc);

#pragma unroll
  for (int mt = 0; mt < 4; mt++) {
    const int r = m0 + wm * 64 + mt * 16 + g;
#pragma unroll
    for (int nt = 0; nt < 4; nt++) {
      const int c = n0 + wn * 32 + nt * 8 + 2 * tig;
      const float b0 = __ldg(bias + c), b1 = __ldg(bias + c + 1);
      float2 v0 = {acc[mt][nt][0] + b0, acc[mt][nt][1] + b1};
      float2 v1 = {acc[mt][nt][2] + b0, acc[mt][nt][3] + b1};
      *(float2*)(C + (size_t)r * N + c) = v0;
      *(float2*)(C + (size_t)(r + 8) * N + c) = v1;
    }
  }
}

// ---------------- QKV GEMM with fused RoPE/split epilogue -------------------
// Q: rotated, *QSCALE, perm16. K: rotated, perm16. V: [B,H,Dh,L], L perm16'd.
__global__ __launch_bounds__(256) void gemm_qkv_rope_kernel(
    const __half* __restrict__ A, const __half* __restrict__ BT,
    const float* __restrict__ bias, __half* __restrict__ Q,
    __half* __restrict__ K, __half* __restrict__ V) {
  extern __shared__ __half smh[];
  const int tid = threadIdx.x;
  const int warp = tid >> 5, lane = tid & 31;
  const int wm = warp >> 2, wn = warp & 3;
  const int g = lane >> 2, tig = lane & 3;
  const int m0 = blockIdx.y << 7, n0 = blockIdx.x << 7;

  float acc[4][4][4];
  gemm_tile_compute(A, BT, smh, m0, n0, EMBD, acc);

  const int seg = n0 >> 10;  // 0=q, 1=k, 2=v (block-uniform)

#pragma unroll
  for (int mt = 0; mt < 4; mt++) {
    const int r = m0 + wm * 64 + mt * 16 + g;
#pragma unroll
    for (int nt = 0; nt < 4; nt++) {
      const int c = n0 + wn * 32 + nt * 8 + 2 * tig;  // even column
      const float b0 = __ldg(bias + c), b1 = __ldg(bias + c + 1);
      const int d = c & 63;
      const int h = (c & 1023) >> 6;
      const int i = d >> 1;
      float vals[2][2] = {{acc[mt][nt][0] + b0, acc[mt][nt][1] + b1},
                          {acc[mt][nt][2] + b0, acc[mt][nt][3] + b1}};
#pragma unroll
      for (int rr = 0; rr < 2; rr++) {
        const int m = r + rr * 8;
        const int bb = m >> 11, l = m & 2047;
        const float x1 = vals[rr][0], x2 = vals[rr][1];
        if (seg == 2) {
          const int lp = perm16(l);  // permute keys dim for vectorized PV
          __half* vp = V + ((size_t)(bb * NHEAD + h) * HDIM + d) * SEQ + lp;
          vp[0] = __float2half_rn(x1);
          vp[SEQ] = __float2half_rn(x2);
        } else {
          const float2 cs = g_rope[l * 32 + i];
          float y1 = x1 * cs.x - x2 * cs.y;
          float y2 = x1 * cs.y + x2 * cs.x;
          if (seg == 0) { y1 *= QSCALE; y2 *= QSCALE; }
          const int j = (d & 15) >> 1;
          const int pd = (d & ~15) + (((j & 3) * 2 + (j >> 2)) << 1);
          __half* dp = (seg == 0 ? Q : K) +
                       ((size_t)(bb * NHEAD + h) * SEQ + l) * HDIM + pd;
          *(__half2*)dp = __floats2half2_rn(y1, y2);
        }
      }
    }
  }
}

// ---------------- fp16 tensor-core causal flash attention -------------------
// 128 q-rows per block, 8 warps, BN=64 keys/tile, 3-stage cp.async ring.
// Softmax base-2 with f16x2 ex2; l via all-ones V column; P/V key-permuted
// so all PV fragments are LDS.64.
#define KS_H 80    // K tile row stride (halves)
#define VT_H 80    // Vt tile row stride
#define PS_H 80    // P/Q staging stride
#define KBUF_H (64 * KS_H)
#define VBUF_H (72 * VT_H)   // rows 0..63 data, 64 = ones, 65..71 zero
#define PS_BUF_H (128 * PS_H)
#define FLASH_SMEM ((3 * (KBUF_H + VBUF_H) + PS_BUF_H) * 2 + 3 * 64 * 4)

__global__ __launch_bounds__(256, 2) void flash_mma_kernel(
    const __half* __restrict__ Q, const __half* __restrict__ K,
    const __half* __restrict__ V, const int* __restrict__ amask,
    __half* __restrict__ O) {
  extern __shared__ __half smh[];
  __half* Ksb = smh;                     // 3 stages
  __half* Vtb = Ksb + 3 * KBUF_H;        // 3 stages
  __half* Ps = Vtb + 3 * VBUF_H;
  int* msk = (int*)(Ps + PS_BUF_H);      // [3][64]

  const int tid = threadIdx.x;
  const int warp = tid >> 5, lane = tid & 31;
  const int g = lane >> 2, tig = lane & 3;
  const int bx = (int)(gridDim.x - 1 - blockIdx.x);  // heavy blocks first
  const int h = blockIdx.y, b = blockIdx.z;
  const int q0 = bx << 7;
  const size_t base = (size_t)(b * NHEAD + h) * SEQ * HDIM;
  const size_t vbase = (size_t)(b * NHEAD + h) * HDIM * SEQ;

  // ---- ones/zero rows 64..71 of each V stage (row 64 = 1.0, rest 0) ----
  for (int idx = tid; idx < 3 * 8 * VT_H; idx += 256) {
    const int stg = idx / (8 * VT_H);
    const int rem = idx % (8 * VT_H);
    const int row = 64 + rem / VT_H;
    Vtb[stg * VBUF_H + row * VT_H + (rem % VT_H)] =
        (row == 64) ? __float2half(1.0f) : __float2half(0.0f);
  }

  // ---- stage Q tile (128x64 halves) through Ps, hoist fragments ----
#pragma unroll
  for (int i = 0; i < 4; i++) {
    const int p = tid + (i << 8);
    const int r = p >> 3, c = (p & 7) << 3;
    *(uint4*)(Ps + r * PS_H + c) =
        *(const uint4*)(Q + base + (size_t)(q0 + r) * HDIM + c);
  }
  __syncthreads();
  uint32_t qf[4][4];
  {
    const __half* qb = Ps + (warp * 16 + g) * PS_H;
#pragma unroll
    for (int ks = 0; ks < 4; ks++) {
      const int off = ks * 16 + 4 * tig;
      uint2 q02 = *(const uint2*)(qb + off);
      uint2 q13 = *(const uint2*)(qb + 8 * PS_H + off);
      qf[ks][0] = q02.x;
      qf[ks][2] = q02.y;
      qf[ks][1] = q13.x;
      qf[ks][3] = q13.y;
    }
  }
  __syncthreads();  // Ps becomes per-warp P staging

  auto prefetch = [&](int kt, int stg) {
    const int k0 = kt << 6;
    __half* Ks_ = Ksb + stg * KBUF_H;
    __half* Vt_ = Vtb + stg * VBUF_H;
#pragma unroll
    for (int i = 0; i < 2; i++) {
      const int p = tid + (i << 8);
      const int r = p >> 3, c = (p & 7) << 3;
      uint32_t dk = (uint32_t)__cvta_generic_to_shared(Ks_ + r * KS_H + c);
      CPA16(dk, K + base + (size_t)(k0 + r) * HDIM + c);
      uint32_t dv = (uint32_t)__cvta_generic_to_shared(Vt_ + r * VT_H + c);
      CPA16(dv, V + vbase + (size_t)r * SEQ + k0 + c);
    }
    if (tid < 64) msk[stg * 64 + tid] = amask[b * SEQ + k0 + tid];
    asm volatile("cp.async.commit_group;\n");
  };

  float m0 = -1e30f, m1 = -1e30f;
  float o[9][4];   // o[8] column 64 = running row-sum l
#pragma unroll
  for (int nt = 0; nt < 9; nt++)
#pragma unroll
    for (int c = 0; c < 4; c++) o[nt][c] = 0.0f;

  const int NT = (q0 >> 6) + 2;
  const int rg0 = q0 + warp * 16 + g;

  prefetch(0, 0);
  if (NT > 1) prefetch(1, 1);

  for (int kt = 0; kt < NT; kt++) {
    const int stg = kt % 3;
    if (kt < NT - 1)
      asm volatile("cp.async.wait_group 1;\n");
    else
      asm volatile("cp.async.wait_group 0;\n");
    __syncthreads();  // single barrier: tile kt visible; stage (kt+2)%3 free

    if (kt + 2 < NT) prefetch(kt + 2, (kt + 2) % 3);

    const __half* Ks_ = Ksb + stg * KBUF_H;
    const __half* Vt_ = Vtb + stg * VBUF_H;
    const int* mk = msk + stg * 64;

    // ---- S = Q @ K^T (pre-scaled by log2e/8) ----
    float s[8][4];
#pragma unroll
    for (int nt = 0; nt < 8; nt++)
#pragma unroll
      for (int c = 0; c < 4; c++) s[nt][c] = 0.0f;

#pragma unroll
    for (int ks = 0; ks < 4; ks++) {
      const int off = ks * 16 + 4 * tig;
#pragma unroll
      for (int nt = 0; nt < 8; nt++) {
        uint2 bv = *(const uint2*)(Ks_ + (nt * 8 + g) * KS_H + off);
        uint32_t bf[2] = {bv.x, bv.y};
        mma_f16(s[nt], qf[ks], bf);
      }
    }

    // ---- mask ----
    if (kt >= NT - 2) {
      const int k0 = kt << 6;
#pragma unroll
      for (int nt = 0; nt < 8; nt++) {
        const int cg = k0 + nt * 8 + 2 * tig;
        const int m_a = mk[nt * 8 + 2 * tig], m_b = mk[nt * 8 + 2 * tig + 1];
        if (!(m_a && cg <= rg0)) s[nt][0] = -1e30f;
        if (!(m_b && cg + 1 <= rg0)) s[nt][1] = -1e30f;
        if (!(m_a && cg <= rg0 + 8)) s[nt][2] = -1e30f;
        if (!(m_b && cg + 1 <= rg0 + 8)) s[nt][3] = -1e30f;
      }
    } else {
#pragma unroll
      for (int nt = 0; nt < 8; nt++) {
        const int m_a = mk[nt * 8 + 2 * tig], m_b = mk[nt * 8 + 2 * tig + 1];
        if (!m_a) { s[nt][0] = -1e30f; s[nt][2] = -1e30f; }
        if (!m_b) { s[nt][1] = -1e30f; s[nt][3] = -1e30f; }
      }
    }

    // ---- online softmax (base-2): max, corr, P via f16x2 ex2 ----
    float mx0 = -1e30f, mx1 = -1e30f;
#pragma unroll
    for (int nt = 0; nt < 8; nt++) {
      mx0 = fmaxf(mx0, fmaxf(s[nt][0], s[nt][1]));
      mx1 = fmaxf(mx1, fmaxf(s[nt][2], s[nt][3]));
    }
    mx0 = fmaxf(mx0, __shfl_xor_sync(0xffffffffu, mx0, 1));
    mx0 = fmaxf(mx0, __shfl_xor_sync(0xffffffffu, mx0, 2));
    mx1 = fmaxf(mx1, __shfl_xor_sync(0xffffffffu, mx1, 1));
    mx1 = fmaxf(mx1, __shfl_xor_sync(0xffffffffu, mx1, 2));
    const float nm0 = fmaxf(m0, mx0), nm1 = fmaxf(m1, mx1);
    const float corr0 = ex2f(m0 - nm0), corr1 = ex2f(m1 - nm1);
    m0 = nm0;
    m1 = nm1;

#pragma unroll
    for (int nt = 0; nt < 9; nt++) {
      o[nt][0] *= corr0;
      o[nt][1] *= corr0;
      o[nt][2] *= corr1;
      o[nt][3] *= corr1;
    }

    // ---- P = 2^(s-nm), stored at perm16'd key positions (fp16 pairs) ----
    __half* pr = Ps + (warp * 16 + g) * PS_H;
#pragma unroll
    for (int nt = 0; nt < 8; nt++) {
      const int dl = nt * 8 + 2 * tig;          // natural key index (even)
      const int j = (dl & 15) >> 1;
      const int pc = (dl & ~15) + (((j & 3) * 2 + (j >> 2)) << 1);
      __half2 d01 = __floats2half2_rn(s[nt][0] - nm0, s[nt][1] - nm0);
      __half2 d23 = __floats2half2_rn(s[nt][2] - nm1, s[nt][3] - nm1);
      *(uint32_t*)(pr + pc) = h2ex2(*(uint32_t*)&d01);
      *(uint32_t*)(pr + 8 * PS_H + pc) = h2ex2(*(uint32_t*)&d23);
    }
    __syncwarp();

    // ---- O += P @ [V | ones]  (keys permuted: all fragments LDS.64) ----
    const __half* pb = Ps + (warp * 16 + g) * PS_H;
#pragma unroll
    for (int ks = 0; ks < 4; ks++) {
      const int off = ks * 16 + 4 * tig;
      uint2 a02 = *(const uint2*)(pb + off);
      uint2 a13 = *(const uint2*)(pb + 8 * PS_H + off);
      uint32_t a[4] = {a02.x, a13.x, a02.y, a13.y};
#pragma unroll
      for (int nt = 0; nt < 9; nt++) {
        uint2 bv = *(const uint2*)(Vt_ + (nt * 8 + g) * VT_H + off);
        uint32_t bf[2] = {bv.x, bv.y};
        mma_f16(o[nt], a, bf);
      }
    }
    __syncwarp();
  }

  // ---- l lives in o[8] col 64 (lane tig=0 of each quad); broadcast ----
  const float l0 = __shfl_sync(0xffffffffu, o[8][0], lane & ~3);
  const float l1 = __shfl_sync(0xffffffffu, o[8][2], lane & ~3);
  const float inv0 = 1.0f / l0, inv1 = 1.0f / l1;

  // ---- write O fp16 perm16 to [B, L, H*Dh] for the proj GEMM ----
#pragma unroll
  for (int nt = 0; nt < 8; nt++) {
    const int dl = nt * 8 + 2 * tig;
    const int j = (dl & 15) >> 1;
    const int col = h * HDIM + (dl & ~15) + (((j & 3) * 2 + (j >> 2)) << 1);
    *(__half2*)(O + (size_t)(b * SEQ + rg0) * EMBD + col) =
        __floats2half2_rn(o[nt][0] * inv0, o[nt][1] * inv0);
    *(__half2*)(O + (size_t)(b * SEQ + rg0 + 8) * EMBD + col) =
        __floats2half2_rn(o[nt][2] * inv1, o[nt][3] * inv1);
  }
}

// ---------------------------------------------------------------------------
extern "C" void kernel_launch(void* const* d_in, const int* in_sizes, int n_in,
                              void* d_out, int out_size) {
  const float* x     = (const float*)d_in[0];
  const float* Wqkv  = (const float*)d_in[1];
  const float* bqkv  = (const float*)d_in[2];
  const float* Wproj = (const float*)d_in[3];
  const float* bproj = (const float*)d_in[4];
  const int*   amask = (const int*)d_in[5];
  float* out = (float*)d_out;

  __half *q, *k, *v, *att, *xh, *wqkvT, *wprojT;
  cudaGetSymbolAddress((void**)&q, g_q);
  cudaGetSymbolAddress((void**)&k, g_k);
  cudaGetSymbolAddress((void**)&v, g_v);
  cudaGetSymbolAddress((void**)&att, g_att);
  cudaGetSymbolAddress((void**)&xh, g_xh);
  cudaGetSymbolAddress((void**)&wqkvT, g_wqkvT);
  cudaGetSymbolAddress((void**)&wprojT, g_wprojT);

  cudaFuncSetAttribute(gemm_f16_kernel,
                       cudaFuncAttributeMaxDynamicSharedMemorySize, GEMM_SMEM);
  cudaFuncSetAttribute(gemm_qkv_rope_kernel,
                       cudaFuncAttributeMaxDynamicSharedMemorySize, GEMM_SMEM);
  cudaFuncSetAttribute(flash_mma_kernel,
                       cudaFuncAttributeMaxDynamicSharedMemorySize, FLASH_SMEM);

  // 0. Operand prep (x round+perm16 + rope table; both weight transposes)
  round_permute_rope<<<1184, 256>>>(x, xh, TOKENS * EMBD / 16);
  {
    dim3 gt(96 + 32, EMBD / 32);
    transpose_both_kernel<<<gt, dim3(32, 8)>>>(Wqkv, wqkvT, Wproj, wprojT);
  }

  // 1. QKV projection + fused RoPE/split -> q (*log2e/8), k, v (L-perm)
  dim3 g1(QKVDIM / 128, TOKENS / 128);
  gemm_qkv_rope_kernel<<<g1, 256, GEMM_SMEM>>>(xh, wqkvT, bqkv, q, k, v);

  // 2. Causal flash attention (fp16 tensor cores) -> att (fp16, perm16)
  dim3 g3(SEQ / 128, NHEAD, BATCH);
  flash_mma_kernel<<<g3, 256, FLASH_SMEM>>>(q, k, v, amask, att);

  // 3. Output projection -> fp32 out
  dim3 g4(EMBD / 128, TOKENS / 128);
  gemm_f16_kernel<<<g4, 256, GEMM_SMEM>>>(att, wprojT, bproj, out, EMBD, EMBD);
}

// round 15
// speedup vs baseline: 1.1758x; 1.0087x over previous
#include <cuda_runtime.h>
#include <cuda_fp16.h>
#include <math.h>
#include <cstdint>

// Problem constants: B=4, L=2048, D=1024, H=16, Dh=64, 3D=3072
#define BATCH   4
#define SEQ     2048
#define EMBD    1024
#define NHEAD   16
#define HDIM    64
#define TOKENS  (BATCH * SEQ)            // 8192
#define QKVDIM  (3 * EMBD)               // 3072

// ---------------- scratch (static __device__, no allocation) ----------------
__device__ __half g_q[(size_t)BATCH * NHEAD * SEQ * HDIM];  // /8*log2e, perm16
__device__ __half g_k[(size_t)BATCH * NHEAD * SEQ * HDIM];  // perm16
__device__ __half g_v[(size_t)BATCH * NHEAD * HDIM * SEQ];  // [B,H,Dh,L] natural
__device__ __half g_att[(size_t)TOKENS * EMBD];             // [B,L,D] perm16
__device__ float2 g_rope[(size_t)SEQ * 32];                 // cos/sin table
__device__ __half g_xh[(size_t)TOKENS * EMBD];              // x fp16, perm16
__device__ __half g_wqkvT[(size_t)QKVDIM * EMBD];           // W_qkv^T fp16, perm16
__device__ __half g_wprojT[(size_t)EMBD * EMBD];            // W_proj^T fp16, perm16

// ---------------- helpers ---------------------------------------------------
__device__ __forceinline__ void mma_f16(float* d, const uint32_t* a,
                                        const uint32_t* b) {
  asm volatile(
      "mma.sync.aligned.m16n8k16.row.col.f32.f16.f16.f32 "
      "{%0,%1,%2,%3},{%4,%5,%6,%7},{%8,%9},{%0,%1,%2,%3};"
      : "+f"(d[0]), "+f"(d[1]), "+f"(d[2]), "+f"(d[3])
      : "r"(a[0]), "r"(a[1]), "r"(a[2]), "r"(a[3]), "r"(b[0]), "r"(b[1]));
}

#define CPA16(dst, src) \
  asm volatile("cp.async.cg.shared.global [%0], [%1], 16;\n" ::"r"(dst), "l"(src))

__device__ __forceinline__ float ex2f(float x) {
  float y;
  asm("ex2.approx.f32 %0, %1;" : "=f"(y) : "f"(x));
  return y;
}
__device__ __forceinline__ uint32_t h2ex2(uint32_t x) {
  uint32_t y;
  asm("ex2.approx.f16x2 %0, %1;" : "=r"(y) : "r"(x));
  return y;
}

// 16-group permutation: pair j (0..7) goes to pair position (j&3)*2 + (j>>2).
__device__ __host__ __forceinline__ int perm16(int k) {
  const int j = (k & 15) >> 1;
  return (k & ~15) + (((j & 3) * 2 + (j >> 2)) << 1) + (k & 1);
}

#define QSCALE (0.125f * 1.44269504f)   // 1/sqrt(64) * log2(e)

// ------------- fp16 round + perm16 (x) + RoPE table fill --------------------
__global__ __launch_bounds__(256) void round_permute_rope(
    const float* __restrict__ in, __half* __restrict__ out, int n16) {
  if (blockIdx.x < 256) {
    const int idx = blockIdx.x * 256 + threadIdx.x;
    const int l = idx >> 5, i = idx & 31;
    const float inv_freq = 1.0f / powf(10000.0f, (2.0f * (float)i) / 64.0f);
    float s, c;
    sincosf((float)l * inv_freq, &s, &c);
    g_rope[idx] = make_float2(c, s);
  }
  int i = blockIdx.x * 256 + threadIdx.x;
  const int stride = gridDim.x * 256;
  for (; i < n16; i += stride) {
    const float4* ip = (const float4*)(in + 16 * (size_t)i);
    float v[16];
    *(float4*)(v + 0) = ip[0];
    *(float4*)(v + 4) = ip[1];
    *(float4*)(v + 8) = ip[2];
    *(float4*)(v + 12) = ip[3];
    __half h[16];
#pragma unroll
    for (int j = 0; j < 8; j++) {
      const int pp = (j & 3) * 2 + (j >> 2);
      h[pp * 2] = __float2half_rn(v[2 * j]);
      h[pp * 2 + 1] = __float2half_rn(v[2 * j + 1]);
    }
    uint4* op = (uint4*)(out + 16 * (size_t)i);
    op[0] = *(uint4*)(h);
    op[1] = *(uint4*)(h + 8);
  }
}

// ------------- both weight transposes in ONE launch -------------------------
__global__ __launch_bounds__(256) void transpose_both_kernel(
    const float* __restrict__ Wqkv, __half* __restrict__ outQkv,
    const float* __restrict__ Wproj, __half* __restrict__ outProj) {
  __shared__ float tile[32][33];
  const float* in;
  __half* out;
  int N, bxx;
  if (blockIdx.x < 96) {
    in = Wqkv; out = outQkv; N = QKVDIM; bxx = blockIdx.x;
  } else {
    in = Wproj; out = outProj; N = EMBD; bxx = blockIdx.x - 96;
  }
  const int K = EMBD;
  const int k0 = blockIdx.y * 32, n0 = bxx * 32;
  const int tx = threadIdx.x, ty = threadIdx.y;  // 32 x 8
#pragma unroll
  for (int i = 0; i < 32; i += 8)
    tile[ty + i][tx] = in[(size_t)(k0 + ty + i) * N + n0 + tx];
  __syncthreads();
  const int pk = perm16(tx);
#pragma unroll
  for (int i = 0; i < 32; i += 8) {
    const int n = ty + i;
    out[(size_t)(n0 + n) * K + k0 + pk] = __float2half_rn(tile[tx][n]);
  }
}

// ---------------- GEMM core (fp16 operands, fp32 accum) ---------------------
#define ABS_H 80                        // smem row stride in halves (160B)
#define AB_BUF_H (128 * ABS_H)          // 10240 halves
#define GEMM_SMEM (4 * AB_BUF_H * 2)    // 81920 B

__device__ __forceinline__ void gemm_tile_compute(
    const __half* __restrict__ A, const __half* __restrict__ BT, __half* sm,
    int m0, int n0, int K, float acc[4][4][4]) {
  const int tid = threadIdx.x;
  const int warp = tid >> 5, lane = tid & 31;
  const int wm = warp >> 2, wn = warp & 3;
  const int g = lane >> 2, tig = lane & 3;

#pragma unroll
  for (int i = 0; i < 4; i++)
#pragma unroll
    for (int j = 0; j < 4; j++)
#pragma unroll
      for (int t = 0; t < 4; t++) acc[i][j][t] = 0.0f;

  auto prefetch = [&](int kt, int buf) {
    __half* As = sm + buf * AB_BUF_H;
    __half* Bs = sm + 2 * AB_BUF_H + buf * AB_BUF_H;
    const int k0 = kt << 6;
#pragma unroll
    for (int j = 0; j < 4; j++) {
      const int p = tid + (j << 8);
      const int r = p >> 3, c = (p & 7) << 3;
      uint32_t da = (uint32_t)__cvta_generic_to_shared(As + r * ABS_H + c);
      CPA16(da, A + (size_t)(m0 + r) * K + k0 + c);
      uint32_t db = (uint32_t)__cvta_generic_to_shared(Bs + r * ABS_H + c);
      CPA16(db, BT + (size_t)(n0 + r) * K + k0 + c);
    }
    asm volatile("cp.async.commit_group;\n");
  };

  const int NT = K >> 6;
  prefetch(0, 0);

  for (int kt = 0; kt < NT; kt++) {
    const int buf = kt & 1;
    if (kt + 1 < NT) {
      prefetch(kt + 1, buf ^ 1);
      asm volatile("cp.async.wait_group 1;\n");
    } else {
      asm volatile("cp.async.wait_group 0;\n");
    }
    __syncthreads();

    const __half* As = sm + buf * AB_BUF_H;
    const __half* Bs = sm + 2 * AB_BUF_H + buf * AB_BUF_H;

#pragma unroll
    for (int ks = 0; ks < 4; ks++) {
      const int koff = ks * 16 + 4 * tig;
      uint32_t af[4][4], bf[4][2];
#pragma unroll
      for (int mt = 0; mt < 4; mt++) {
        const int row = wm * 64 + mt * 16 + g;
        uint2 a02 = *(const uint2*)(As + row * ABS_H + koff);
        uint2 a13 = *(const uint2*)(As + (row + 8) * ABS_H + koff);
        af[mt][0] = a02.x;
        af[mt][2] = a02.y;
        af[mt][1] = a13.x;
        af[mt][3] = a13.y;
      }
#pragma unroll
      for (int nt = 0; nt < 4; nt++) {
        const int nrow = wn * 32 + nt * 8 + g;
        uint2 b01 = *(const uint2*)(Bs + nrow * ABS_H + koff);
        bf[nt][0] = b01.x;
        bf[nt][1] = b01.y;
      }
#pragma unroll
      for (int mt = 0; mt < 4; mt++)
#pragma unroll
        for (int nt = 0; nt < 4; nt++) mma_f16(acc[mt][nt], af[mt], bf[nt]);
    }
    __syncthreads();
  }
}

// ---------------- plain GEMM + bias (proj, fp32 out) ------------------------
__global__ __launch_bounds__(256) void gemm_f16_kernel(
    const __half* __restrict__ A, const __half* __restrict__ BT,
    const float* __restrict__ bias, float* __restrict__ C, int N, int K) {
  extern __shared__ __half smh[];
  const int tid = threadIdx.x;
  const int warp = tid >> 5, lane = tid & 31;
  const int wm = warp >> 2, wn = warp & 3;
  const int g = lane >> 2, tig = lane & 3;
  const int m0 = blockIdx.y << 7, n0 = blockIdx.x << 7;

  float acc[4][4][4];
  gemm_tile_compute(A, BT, smh, m0, n0, K, acc);

#pragma unroll
  for (int mt = 0; mt < 4; mt++) {
    const int r = m0 + wm * 64 + mt * 16 + g;
#pragma unroll
    for (int nt = 0; nt < 4; nt++) {
      const int c = n0 + wn * 32 + nt * 8 + 2 * tig;
      const float b0 = __ldg(bias + c), b1 = __ldg(bias + c + 1);
      float2 v0 = {acc[mt][nt][0] + b0, acc[mt][nt][1] + b1};
      float2 v1 = {acc[mt][nt][2] + b0, acc[mt][nt][3] + b1};
      *(float2*)(C + (size_t)r * N + c) = v0;
      *(float2*)(C + (size_t)(r + 8) * N + c) = v1;
    }
  }
}

// ---------------- QKV GEMM with fused RoPE/split epilogue -------------------
// Q: rotated, *QSCALE, perm16. K: rotated, perm16. V: [B,H,Dh,L] natural.
__global__ __launch_bounds__(256) void gemm_qkv_rope_kernel(
    const __half* __restrict__ A, const __half* __restrict__ BT,
    const float* __restrict__ bias, __half* __restrict__ Q,
    __half* __restrict__ K, __half* __restrict__ V) {
  extern __shared__ __half smh[];
  const int tid = threadIdx.x;
  const int warp = tid >> 5, lane = tid & 31;
  const int wm = warp >> 2, wn = warp & 3;
  const int g = lane >> 2, tig = lane & 3;
  const int m0 = blockIdx.y << 7, n0 = blockIdx.x << 7;

  float acc[4][4][4];
  gemm_tile_compute(A, BT, smh, m0, n0, EMBD, acc);

  const int seg = n0 >> 10;  // 0=q, 1=k, 2=v (block-uniform)

#pragma unroll
  for (int mt = 0; mt < 4; mt++) {
    const int r = m0 + wm * 64 + mt * 16 + g;
#pragma unroll
    for (int nt = 0; nt < 4; nt++) {
      const int c = n0 + wn * 32 + nt * 8 + 2 * tig;  // even column
      const float b0 = __ldg(bias + c), b1 = __ldg(bias + c + 1);
      const int d = c & 63;
      const int h = (c & 1023) >> 6;
      const int i = d >> 1;
      float vals[2][2] = {{acc[mt][nt][0] + b0, acc[mt][nt][1] + b1},
                          {acc[mt][nt][2] + b0, acc[mt][nt][3] + b1}};
#pragma unroll
      for (int rr = 0; rr < 2; rr++) {
        const int m = r + rr * 8;
        const int bb = m >> 11, l = m & 2047;
        const float x1 = vals[rr][0], x2 = vals[rr][1];
        if (seg == 2) {
          __half* vp = V + ((size_t)(bb * NHEAD + h) * HDIM + d) * SEQ + l;
          vp[0] = __float2half_rn(x1);
          vp[SEQ] = __float2half_rn(x2);
        } else {
          const float2 cs = g_rope[l * 32 + i];
          float y1 = x1 * cs.x - x2 * cs.y;
          float y2 = x1 * cs.y + x2 * cs.x;
          if (seg == 0) { y1 *= QSCALE; y2 *= QSCALE; }
          const int j = (d & 15) >> 1;
          const int pd = (d & ~15) + (((j & 3) * 2 + (j >> 2)) << 1);
          __half* dp = (seg == 0 ? Q : K) +
                       ((size_t)(bb * NHEAD + h) * SEQ + l) * HDIM + pd;
          *(__half2*)dp = __floats2half2_rn(y1, y2);
        }
      }
    }
  }
}

// ---------------- fp16 tensor-core causal flash attention -------------------
// 128 q-rows per block, 8 warps, BN=64 keys/tile, 3-stage cp.async ring.
// P kept entirely in registers (C-frag == A-frag packing); no smem staging.
// Q fragments loaded directly from gmem. l via all-ones V column.
#define KS_H 80    // K tile row stride (halves)
#define VT_H 72    // Vt tile row stride
#define KBUF_H (64 * KS_H)
#define VBUF_H (72 * VT_H)   // rows 0..63 data, 64 = ones, 65..71 zero
#define FLASH_SMEM ((3 * (KBUF_H + VBUF_H)) * 2 + 3 * 64 * 4)

__global__ __launch_bounds__(256, 2) void flash_mma_kernel(
    const __half* __restrict__ Q, const __half* __restrict__ K,
    const __half* __restrict__ V, const int* __restrict__ amask,
    __half* __restrict__ O) {
  extern __shared__ __half smh[];
  __half* Ksb = smh;                     // 3 stages
  __half* Vtb = Ksb + 3 * KBUF_H;        // 3 stages
  int* msk = (int*)(Vtb + 3 * VBUF_H);   // [3][64]

  const int tid = threadIdx.x;
  const int warp = tid >> 5, lane = tid & 31;
  const int g = lane >> 2, tig = lane & 3;
  const int bx = (int)(gridDim.x - 1 - blockIdx.x);  // heavy blocks first
  const int h = blockIdx.y, b = blockIdx.z;
  const int q0 = bx << 7;
  const size_t base = (size_t)(b * NHEAD + h) * SEQ * HDIM;
  const size_t vbase = (size_t)(b * NHEAD + h) * HDIM * SEQ;

  const int NT = (q0 >> 6) + 2;
  const int rg0 = q0 + warp * 16 + g;

  // ---- ones/zero rows 64..71 of each V stage (row 64 = 1.0, rest 0) ----
  for (int idx = tid; idx < 3 * 8 * VT_H; idx += 256) {
    const int stg = idx / (8 * VT_H);
    const int rem = idx % (8 * VT_H);
    const int row = 64 + rem / VT_H;
    Vtb[stg * VBUF_H + row * VT_H + (rem % VT_H)] =
        (row == 64) ? __float2half(1.0f) : __float2half(0.0f);
  }

  // ---- Q fragments straight from gmem (perm16 layout -> uint2 pairs) ----
  uint32_t qf[4][4];
  {
    const __half* q0p = Q + base + (size_t)rg0 * HDIM;
    const __half* q1p = q0p + 8 * HDIM;
#pragma unroll
    for (int ks = 0; ks < 4; ks++) {
      const int off = ks * 16 + 4 * tig;
      uint2 a02 = __ldg((const uint2*)(q0p + off));
      uint2 a13 = __ldg((const uint2*)(q1p + off));
      qf[ks][0] = a02.x;
      qf[ks][2] = a02.y;
      qf[ks][1] = a13.x;
      qf[ks][3] = a13.y;
    }
  }

  auto prefetch = [&](int kt, int stg) {
    const int k0 = kt << 6;
    __half* Ks_ = Ksb + stg * KBUF_H;
    __half* Vt_ = Vtb + stg * VBUF_H;
#pragma unroll
    for (int i = 0; i < 2; i++) {
      const int p = tid + (i << 8);
      const int r = p >> 3, c = (p & 7) << 3;
      uint32_t dk = (uint32_t)__cvta_generic_to_shared(Ks_ + r * KS_H + c);
      CPA16(dk, K + base + (size_t)(k0 + r) * HDIM + c);
      uint32_t dv = (uint32_t)__cvta_generic_to_shared(Vt_ + r * VT_H + c);
      CPA16(dv, V + vbase + (size_t)r * SEQ + k0 + c);
    }
    if (tid < 64) msk[stg * 64 + tid] = amask[b * SEQ + k0 + tid];
    asm volatile("cp.async.commit_group;\n");
  };

  float m0 = -1e30f, m1 = -1e30f;
  float o[9][4];   // o[8] column 64 = running row-sum l
#pragma unroll
  for (int nt = 0; nt < 9; nt++)
#pragma unroll
    for (int c = 0; c < 4; c++) o[nt][c] = 0.0f;

  prefetch(0, 0);
  if (NT > 1) prefetch(1, 1);
  __syncthreads();  // ones rows visible before first PV

  for (int kt = 0; kt < NT; kt++) {
    const int stg = kt % 3;
    if (kt < NT - 1)
      asm volatile("cp.async.wait_group 1;\n");
    else
      asm volatile("cp.async.wait_group 0;\n");
    __syncthreads();  // tile kt visible; stage (kt+2)%3 free

    if (kt + 2 < NT) prefetch(kt + 2, (kt + 2) % 3);

    const __half* Ks_ = Ksb + stg * KBUF_H;
    const __half* Vt_ = Vtb + stg * VBUF_H;
    const int* mk = msk + stg * 64;

    // ---- S = Q @ K^T (pre-scaled by log2e/8) ----
    float s[8][4];
#pragma unroll
    for (int nt = 0; nt < 8; nt++)
#pragma unroll
      for (int c = 0; c < 4; c++) s[nt][c] = 0.0f;

#pragma unroll
    for (int ks = 0; ks < 4; ks++) {
      const int off = ks * 16 + 4 * tig;
#pragma unroll
      for (int nt = 0; nt < 8; nt++) {
        uint2 bv = *(const uint2*)(Ks_ + (nt * 8 + g) * KS_H + off);
        uint32_t bf[2] = {bv.x, bv.y};
        mma_f16(s[nt], qf[ks], bf);
      }
    }

    // ---- mask ----
    if (kt >= NT - 2) {
      const int k0 = kt << 6;
#pragma unroll
      for (int nt = 0; nt < 8; nt++) {
        const int cg = k0 + nt * 8 + 2 * tig;
        const int m_a = mk[nt * 8 + 2 * tig], m_b = mk[nt * 8 + 2 * tig + 1];
        if (!(m_a && cg <= rg0)) s[nt][0] = -1e30f;
        if (!(m_b && cg + 1 <= rg0)) s[nt][1] = -1e30f;
        if (!(m_a && cg <= rg0 + 8)) s[nt][2] = -1e30f;
        if (!(m_b && cg + 1 <= rg0 + 8)) s[nt][3] = -1e30f;
      }
    } else {
#pragma unroll
      for (int nt = 0; nt < 8; nt++) {
        const int m_a = mk[nt * 8 + 2 * tig], m_b = mk[nt * 8 + 2 * tig + 1];
        if (!m_a) { s[nt][0] = -1e30f; s[nt][2] = -1e30f; }
        if (!m_b) { s[nt][1] = -1e30f; s[nt][3] = -1e30f; }
      }
    }

    // ---- online softmax (base-2): max, corr ----
    float mx0 = -1e30f, mx1 = -1e30f;
#pragma unroll
    for (int nt = 0; nt < 8; nt++) {
      mx0 = fmaxf(mx0, fmaxf(s[nt][0], s[nt][1]));
      mx1 = fmaxf(mx1, fmaxf(s[nt][2], s[nt][3]));
    }
    mx0 = fmaxf(mx0, __shfl_xor_sync(0xffffffffu, mx0, 1));
    mx0 = fmaxf(mx0, __shfl_xor_sync(0xffffffffu, mx0, 2));
    mx1 = fmaxf(mx1, __shfl_xor_sync(0xffffffffu, mx1, 1));
    mx1 = fmaxf(mx1, __shfl_xor_sync(0xffffffffu, mx1, 2));
    const float nm0 = fmaxf(m0, mx0), nm1 = fmaxf(m1, mx1);
    const float corr0 = ex2f(m0 - nm0), corr1 = ex2f(m1 - nm1);
    m0 = nm0;
    m1 = nm1;

#pragma unroll
    for (int nt = 0; nt < 9; nt++) {
      o[nt][0] *= corr0;
      o[nt][1] *= corr0;
      o[nt][2] *= corr1;
      o[nt][3] *= corr1;
    }

    // ---- P = 2^(s-nm) packed in registers: C-frag IS the PV A-frag ----
    uint32_t p0[8], p1[8];
#pragma unroll
    for (int nt = 0; nt < 8; nt++) {
      __half2 d01 = __floats2half2_rn(s[nt][0] - nm0, s[nt][1] - nm0);
      __half2 d23 = __floats2half2_rn(s[nt][2] - nm1, s[nt][3] - nm1);
      p0[nt] = h2ex2(*(uint32_t*)&d01);
      p1[nt] = h2ex2(*(uint32_t*)&d23);
    }

    // ---- O += P @ [V | ones] (nt=8 column accumulates row-sum l) ----
#pragma unroll
    for (int ks = 0; ks < 4; ks++) {
      const int off = ks * 16 + 2 * tig;
      uint32_t a[4] = {p0[2 * ks], p1[2 * ks], p0[2 * ks + 1], p1[2 * ks + 1]};
#pragma unroll
      for (int nt = 0; nt < 9; nt++) {
        const __half* vb = Vt_ + (nt * 8 + g) * VT_H + off;
        uint32_t bf[2];
        bf[0] = *(const uint32_t*)(vb);
        bf[1] = *(const uint32_t*)(vb + 8);
        mma_f16(o[nt], a, bf);
      }
    }
  }

  // ---- l lives in o[8] col 64 (tig=0 of each quad); broadcast ----
  const float l0 = __shfl_sync(0xffffffffu, o[8][0], lane & ~3);
  const float l1 = __shfl_sync(0xffffffffu, o[8][2], lane & ~3);
  const float inv0 = 1.0f / l0, inv1 = 1.0f / l1;

  // ---- write O fp16 perm16 to [B, L, H*Dh] for the proj GEMM ----
#pragma unroll
  for (int nt = 0; nt < 8; nt++) {
    const int dl = nt * 8 + 2 * tig;
    const int j = (dl & 15) >> 1;
    const int col = h * HDIM + (dl & ~15) + (((j & 3) * 2 + (j >> 2)) << 1);
    *(__half2*)(O + (size_t)(b * SEQ + rg0) * EMBD + col) =
        __floats2half2_rn(o[nt][0] * inv0, o[nt][1] * inv0);
    *(__half2*)(O + (size_t)(b * SEQ + rg0 + 8) * EMBD + col) =
        __floats2half2_rn(o[nt][2] * inv1, o[nt][3] * inv1);
  }
}

// ---------------------------------------------------------------------------
extern "C" void kernel_launch(void* const* d_in, const int* in_sizes, int n_in,
                              void* d_out, int out_size) {
  const float* x     = (const float*)d_in[0];
  const float* Wqkv  = (const float*)d_in[1];
  const float* bqkv  = (const float*)d_in[2];
  const float* Wproj = (const float*)d_in[3];
  const float* bproj = (const float*)d_in[4];
  const int*   amask = (const int*)d_in[5];
  float* out = (float*)d_out;

  __half *q, *k, *v, *att, *xh, *wqkvT, *wprojT;
  cudaGetSymbolAddress((void**)&q, g_q);
  cudaGetSymbolAddress((void**)&k, g_k);
  cudaGetSymbolAddress((void**)&v, g_v);
  cudaGetSymbolAddress((void**)&att, g_att);
  cudaGetSymbolAddress((void**)&xh, g_xh);
  cudaGetSymbolAddress((void**)&wqkvT, g_wqkvT);
  cudaGetSymbolAddress((void**)&wprojT, g_wprojT);

  cudaFuncSetAttribute(gemm_f16_kernel,
                       cudaFuncAttributeMaxDynamicSharedMemorySize, GEMM_SMEM);
  cudaFuncSetAttribute(gemm_qkv_rope_kernel,
                       cudaFuncAttributeMaxDynamicSharedMemorySize, GEMM_SMEM);
  cudaFuncSetAttribute(flash_mma_kernel,
                       cudaFuncAttributeMaxDynamicSharedMemorySize, FLASH_SMEM);

  // 0. Operand prep (x round+perm16 + rope table; both weight transposes)
  round_permute_rope<<<1184, 256>>>(x, xh, TOKENS * EMBD / 16);
  {
    dim3 gt(96 + 32, EMBD / 32);
    transpose_both_kernel<<<gt, dim3(32, 8)>>>(Wqkv, wqkvT, Wproj, wprojT);
  }

  // 1. QKV projection + fused RoPE/split -> q (*log2e/8), k, v
  dim3 g1(QKVDIM / 128, TOKENS / 128);
  gemm_qkv_rope_kernel<<<g1, 256, GEMM_SMEM>>>(xh, wqkvT, bqkv, q, k, v);

  // 2. Causal flash attention (fp16 tensor cores) -> att (fp16, perm16)
  dim3 g3(SEQ / 128, NHEAD, BATCH);
  flash_mma_kernel<<<g3, 256, FLASH_SMEM>>>(q, k, v, amask, att);

  // 3. Output projection -> fp32 out
  dim3 g4(EMBD / 128, TOKENS / 128);
  gemm_f16_kernel<<<g4, 256, GEMM_SMEM>>>(att, wprojT, bproj, out, EMBD, EMBD);
}

// round 16
// speedup vs baseline: 1.2029x; 1.0230x over previous
#include <cuda_runtime.h>
#include <cuda_fp16.h>
#include <math.h>
#include <cstdint>

// Problem constants: B=4, L=2048, D=1024, H=16, Dh=64, 3D=3072
#define BATCH   4
#define SEQ     2048
#define EMBD    1024
#define NHEAD   16
#define HDIM    64
#define TOKENS  (BATCH * SEQ)            // 8192
#define QKVDIM  (3 * EMBD)               // 3072

// ---------------- scratch (static __device__, no allocation) ----------------
__device__ __half g_q[(size_t)BATCH * NHEAD * SEQ * HDIM];  // /8*log2e, perm16
__device__ __half g_k[(size_t)BATCH * NHEAD * SEQ * HDIM];  // perm16
__device__ __half g_v[(size_t)BATCH * NHEAD * HDIM * SEQ];  // [B,H,Dh,L] natural
__device__ __half g_att[(size_t)TOKENS * EMBD];             // [B,L,D] perm16
__device__ float2 g_rope[(size_t)SEQ * 32];                 // cos/sin table
__device__ __half g_xh[(size_t)TOKENS * EMBD];              // x fp16, perm16
__device__ __half g_wqkvT[(size_t)QKVDIM * EMBD];           // W_qkv^T fp16, perm16
__device__ __half g_wprojT[(size_t)EMBD * EMBD];            // W_proj^T fp16, perm16

// ---------------- helpers ---------------------------------------------------
__device__ __forceinline__ void mma_f16(float* d, const uint32_t* a,
                                        const uint32_t* b) {
  asm volatile(
      "mma.sync.aligned.m16n8k16.row.col.f32.f16.f16.f32 "
      "{%0,%1,%2,%3},{%4,%5,%6,%7},{%8,%9},{%0,%1,%2,%3};"
      : "+f"(d[0]), "+f"(d[1]), "+f"(d[2]), "+f"(d[3])
      : "r"(a[0]), "r"(a[1]), "r"(a[2]), "r"(a[3]), "r"(b[0]), "r"(b[1]));
}

#define CPA16(dst, src) \
  asm volatile("cp.async.cg.shared.global [%0], [%1], 16;\n" ::"r"(dst), "l"(src))

__device__ __forceinline__ float ex2f(float x) {
  float y;
  asm("ex2.approx.f32 %0, %1;" : "=f"(y) : "f"(x));
  return y;
}
__device__ __forceinline__ uint32_t h2ex2(uint32_t x) {
  uint32_t y;
  asm("ex2.approx.f16x2 %0, %1;" : "=r"(y) : "r"(x));
  return y;
}

// 16-group permutation: pair j (0..7) goes to pair position (j&3)*2 + (j>>2).
__device__ __host__ __forceinline__ int perm16(int k) {
  const int j = (k & 15) >> 1;
  return (k & ~15) + (((j & 3) * 2 + (j >> 2)) << 1) + (k & 1);
}

#define QSCALE (0.125f * 1.44269504f)   // 1/sqrt(64) * log2(e)

// ------------- fp16 round + perm16 (x) + RoPE table fill --------------------
__global__ __launch_bounds__(256) void round_permute_rope(
    const float* __restrict__ in, __half* __restrict__ out, int n16) {
  if (blockIdx.x < 256) {
    const int idx = blockIdx.x * 256 + threadIdx.x;
    const int l = idx >> 5, i = idx & 31;
    const float inv_freq = 1.0f / powf(10000.0f, (2.0f * (float)i) / 64.0f);
    float s, c;
    sincosf((float)l * inv_freq, &s, &c);
    g_rope[idx] = make_float2(c, s);
  }
  int i = blockIdx.x * 256 + threadIdx.x;
  const int stride = gridDim.x * 256;
  for (; i < n16; i += stride) {
    const float4* ip = (const float4*)(in + 16 * (size_t)i);
    float v[16];
    *(float4*)(v + 0) = ip[0];
    *(float4*)(v + 4) = ip[1];
    *(float4*)(v + 8) = ip[2];
    *(float4*)(v + 12) = ip[3];
    __half h[16];
#pragma unroll
    for (int j = 0; j < 8; j++) {
      const int pp = (j & 3) * 2 + (j >> 2);
      h[pp * 2] = __float2half_rn(v[2 * j]);
      h[pp * 2 + 1] = __float2half_rn(v[2 * j + 1]);
    }
    uint4* op = (uint4*)(out + 16 * (size_t)i);
    op[0] = *(uint4*)(h);
    op[1] = *(uint4*)(h + 8);
  }
}

// ------------- both weight transposes in ONE launch -------------------------
__global__ __launch_bounds__(256) void transpose_both_kernel(
    const float* __restrict__ Wqkv, __half* __restrict__ outQkv,
    const float* __restrict__ Wproj, __half* __restrict__ outProj) {
  __shared__ float tile[32][33];
  const float* in;
  __half* out;
  int N, bxx;
  if (blockIdx.x < 96) {
    in = Wqkv; out = outQkv; N = QKVDIM; bxx = blockIdx.x;
  } else {
    in = Wproj; out = outProj; N = EMBD; bxx = blockIdx.x - 96;
  }
  const int K = EMBD;
  const int k0 = blockIdx.y * 32, n0 = bxx * 32;
  const int tx = threadIdx.x, ty = threadIdx.y;  // 32 x 8
#pragma unroll
  for (int i = 0; i < 32; i += 8)
    tile[ty + i][tx] = in[(size_t)(k0 + ty + i) * N + n0 + tx];
  __syncthreads();
  const int pk = perm16(tx);
#pragma unroll
  for (int i = 0; i < 32; i += 8) {
    const int n = ty + i;
    out[(size_t)(n0 + n) * K + k0 + pk] = __float2half_rn(tile[tx][n]);
  }
}

// ---------------- GEMM core (fp16 operands, fp32 accum) ---------------------
#define ABS_H 80                        // smem row stride in halves (160B)
#define AB_BUF_H (128 * ABS_H)          // 10240 halves
#define GEMM_SMEM (4 * AB_BUF_H * 2)    // 81920 B

__device__ __forceinline__ void gemm_tile_compute(
    const __half* __restrict__ A, const __half* __restrict__ BT, __half* sm,
    int m0, int n0, int K, float acc[4][4][4]) {
  const int tid = threadIdx.x;
  const int warp = tid >> 5, lane = tid & 31;
  const int wm = warp >> 2, wn = warp & 3;
  const int g = lane >> 2, tig = lane & 3;

#pragma unroll
  for (int i = 0; i < 4; i++)
#pragma unroll
    for (int j = 0; j < 4; j++)
#pragma unroll
      for (int t = 0; t < 4; t++) acc[i][j][t] = 0.0f;

  auto prefetch = [&](int kt, int buf) {
    __half* As = sm + buf * AB_BUF_H;
    __half* Bs = sm + 2 * AB_BUF_H + buf * AB_BUF_H;
    const int k0 = kt << 6;
#pragma unroll
    for (int j = 0; j < 4; j++) {
      const int p = tid + (j << 8);
      const int r = p >> 3, c = (p & 7) << 3;
      uint32_t da = (uint32_t)__cvta_generic_to_shared(As + r * ABS_H + c);
      CPA16(da, A + (size_t)(m0 + r) * K + k0 + c);
      uint32_t db = (uint32_t)__cvta_generic_to_shared(Bs + r * ABS_H + c);
      CPA16(db, BT + (size_t)(n0 + r) * K + k0 + c);
    }
    asm volatile("cp.async.commit_group;\n");
  };

  const int NT = K >> 6;
  prefetch(0, 0);

  for (int kt = 0; kt < NT; kt++) {
    const int buf = kt & 1;
    if (kt + 1 < NT) {
      prefetch(kt + 1, buf ^ 1);
      asm volatile("cp.async.wait_group 1;\n");
    } else {
      asm volatile("cp.async.wait_group 0;\n");
    }
    __syncthreads();

    const __half* As = sm + buf * AB_BUF_H;
    const __half* Bs = sm + 2 * AB_BUF_H + buf * AB_BUF_H;

#pragma unroll
    for (int ks = 0; ks < 4; ks++) {
      const int koff = ks * 16 + 4 * tig;
      uint32_t af[4][4], bf[4][2];
#pragma unroll
      for (int mt = 0; mt < 4; mt++) {
        const int row = wm * 64 + mt * 16 + g;
        uint2 a02 = *(const uint2*)(As + row * ABS_H + koff);
        uint2 a13 = *(const uint2*)(As + (row + 8) * ABS_H + koff);
        af[mt][0] = a02.x;
        af[mt][2] = a02.y;
        af[mt][1] = a13.x;
        af[mt][3] = a13.y;
      }
#pragma unroll
      for (int nt = 0; nt < 4; nt++) {
        const int nrow = wn * 32 + nt * 8 + g;
        uint2 b01 = *(const uint2*)(Bs + nrow * ABS_H + koff);
        bf[nt][0] = b01.x;
        bf[nt][1] = b01.y;
      }
#pragma unroll
      for (int mt = 0; mt < 4; mt++)
#pragma unroll
        for (int nt = 0; nt < 4; nt++) mma_f16(acc[mt][nt], af[mt], bf[nt]);
    }
    __syncthreads();
  }
}

// ---------------- plain GEMM + bias (proj, fp32 out) ------------------------
__global__ __launch_bounds__(256) void gemm_f16_kernel(
    const __half* __restrict__ A, const __half* __restrict__ BT,
    const float* __restrict__ bias, float* __restrict__ C, int N, int K) {
  extern __shared__ __half smh[];
  const int tid = threadIdx.x;
  const int warp = tid >> 5, lane = tid & 31;
  const int wm = warp >> 2, wn = warp & 3;
  const int g = lane >> 2, tig = lane & 3;
  const int m0 = blockIdx.y << 7, n0 = blockIdx.x << 7;

  float acc[4][4][4];
  gemm_tile_compute(A, BT, smh, m0, n0, K, acc);

#pragma unroll
  for (int mt = 0; mt < 4; mt++) {
    const int r = m0 + wm * 64 + mt * 16 + g;
#pragma unroll
    for (int nt = 0; nt < 4; nt++) {
      const int c = n0 + wn * 32 + nt * 8 + 2 * tig;
      const float b0 = __ldg(bias + c), b1 = __ldg(bias + c + 1);
      float2 v0 = {acc[mt][nt][0] + b0, acc[mt][nt][1] + b1};
      float2 v1 = {acc[mt][nt][2] + b0, acc[mt][nt][3] + b1};
      *(float2*)(C + (size_t)r * N + c) = v0;
      *(float2*)(C + (size_t)(r + 8) * N + c) = v1;
    }
  }
}

// ---------------- QKV GEMM with fused RoPE/split epilogue -------------------
// Q: rotated, *QSCALE, perm16. K: rotated, perm16. V: [B,H,Dh,L] natural.
__global__ __launch_bounds__(256) void gemm_qkv_rope_kernel(
    const __half* __restrict__ A, const __half* __restrict__ BT,
    const float* __restrict__ bias, __half* __restrict__ Q,
    __half* __restrict__ K, __half* __restrict__ V) {
  extern __shared__ __half smh[];
  const int tid = threadIdx.x;
  const int warp = tid >> 5, lane = tid & 31;
  const int wm = warp >> 2, wn = warp & 3;
  const int g = lane >> 2, tig = lane & 3;
  const int m0 = blockIdx.y << 7, n0 = blockIdx.x << 7;

  float acc[4][4][4];
  gemm_tile_compute(A, BT, smh, m0, n0, EMBD, acc);

  const int seg = n0 >> 10;  // 0=q, 1=k, 2=v (block-uniform)

#pragma unroll
  for (int mt = 0; mt < 4; mt++) {
    const int r = m0 + wm * 64 + mt * 16 + g;
#pragma unroll
    for (int nt = 0; nt < 4; nt++) {
      const int c = n0 + wn * 32 + nt * 8 + 2 * tig;  // even column
      const float b0 = __ldg(bias + c), b1 = __ldg(bias + c + 1);
      const int d = c & 63;
      const int h = (c & 1023) >> 6;
      const int i = d >> 1;
      float vals[2][2] = {{acc[mt][nt][0] + b0, acc[mt][nt][1] + b1},
                          {acc[mt][nt][2] + b0, acc[mt][nt][3] + b1}};
#pragma unroll
      for (int rr = 0; rr < 2; rr++) {
        const int m = r + rr * 8;
        const int bb = m >> 11, l = m & 2047;
        const float x1 = vals[rr][0], x2 = vals[rr][1];
        if (seg == 2) {
          __half* vp = V + ((size_t)(bb * NHEAD + h) * HDIM + d) * SEQ + l;
          vp[0] = __float2half_rn(x1);
          vp[SEQ] = __float2half_rn(x2);
        } else {
          const float2 cs = g_rope[l * 32 + i];
          float y1 = x1 * cs.x - x2 * cs.y;
          float y2 = x1 * cs.y + x2 * cs.x;
          if (seg == 0) { y1 *= QSCALE; y2 *= QSCALE; }
          const int j = (d & 15) >> 1;
          const int pd = (d & ~15) + (((j & 3) * 2 + (j >> 2)) << 1);
          __half* dp = (seg == 0 ? Q : K) +
                       ((size_t)(bb * NHEAD + h) * SEQ + l) * HDIM + pd;
          *(__half2*)dp = __floats2half2_rn(y1, y2);
        }
      }
    }
  }
}

// ---------------- fp16 tensor-core causal flash attention -------------------
// 128 q-rows per block, 8 warps. 128-key double-buffered stages, each computed
// as two 64-key sub-tiles sharing ONE barrier + prefetch. P in registers.
#define KS_H 80     // K tile row stride (halves); rows = 128 keys
#define VT_H 136    // Vt tile row stride (128 keys + 8 pad); rows = dh + ones
#define KBUF_H (128 * KS_H)   // 10240
#define VBUF_H (72 * VT_H)    // 9792: rows 0..63 data, 64 ones, 65..71 zero
#define FLASH_SMEM ((2 * (KBUF_H + VBUF_H)) * 2 + 2 * 128 * 4)  // 81152 B

__global__ __launch_bounds__(256, 2) void flash_mma_kernel(
    const __half* __restrict__ Q, const __half* __restrict__ K,
    const __half* __restrict__ V, const int* __restrict__ amask,
    __half* __restrict__ O) {
  extern __shared__ __half smh[];
  __half* Ksb = smh;                     // 2 stages
  __half* Vtb = Ksb + 2 * KBUF_H;        // 2 stages
  int* msk = (int*)(Vtb + 2 * VBUF_H);   // [2][128]

  const int tid = threadIdx.x;
  const int warp = tid >> 5, lane = tid & 31;
  const int g = lane >> 2, tig = lane & 3;
  const int bx = (int)(gridDim.x - 1 - blockIdx.x);  // heavy blocks first
  const int h = blockIdx.y, b = blockIdx.z;
  const int q0 = bx << 7;
  const size_t base = (size_t)(b * NHEAD + h) * SEQ * HDIM;
  const size_t vbase = (size_t)(b * NHEAD + h) * HDIM * SEQ;

  const int NS = bx + 1;                 // 128-key stages
  const int rg0 = q0 + warp * 16 + g;

  // ---- ones/zero rows 64..71 of both V stages (row 64 = 1.0, rest 0) ----
  for (int idx = tid; idx < 2 * 8 * VT_H; idx += 256) {
    const int stg = idx / (8 * VT_H);
    const int rem = idx % (8 * VT_H);
    const int row = 64 + rem / VT_H;
    Vtb[stg * VBUF_H + row * VT_H + (rem % VT_H)] =
        (row == 64) ? __float2half(1.0f) : __float2half(0.0f);
  }

  // ---- Q fragments straight from gmem (perm16 layout -> uint2 pairs) ----
  uint32_t qf[4][4];
  {
    const __half* q0p = Q + base + (size_t)rg0 * HDIM;
    const __half* q1p = q0p + 8 * HDIM;
#pragma unroll
    for (int ks = 0; ks < 4; ks++) {
      const int off = ks * 16 + 4 * tig;
      uint2 a02 = __ldg((const uint2*)(q0p + off));
      uint2 a13 = __ldg((const uint2*)(q1p + off));
      qf[ks][0] = a02.x;
      qf[ks][2] = a02.y;
      qf[ks][1] = a13.x;
      qf[ks][3] = a13.y;
    }
  }

  auto prefetch = [&](int st, int buf) {
    const int k0 = st << 7;
    __half* Ks_ = Ksb + buf * KBUF_H;
    __half* Vt_ = Vtb + buf * VBUF_H;
#pragma unroll
    for (int i = 0; i < 4; i++) {
      const int p = tid + (i << 8);
      // K: 128 rows x 8 16B-chunks
      const int kr = p >> 3, kc = (p & 7) << 3;
      uint32_t dk = (uint32_t)__cvta_generic_to_shared(Ks_ + kr * KS_H + kc);
      CPA16(dk, K + base + (size_t)(k0 + kr) * HDIM + kc);
      // V: 64 rows x 16 16B-chunks (128 keys)
      const int vr = p >> 4, vc = (p & 15) << 3;
      uint32_t dv = (uint32_t)__cvta_generic_to_shared(Vt_ + vr * VT_H + vc);
      CPA16(dv, V + vbase + (size_t)vr * SEQ + k0 + vc);
    }
    if (tid < 128) msk[buf * 128 + tid] = amask[b * SEQ + k0 + tid];
    asm volatile("cp.async.commit_group;\n");
  };

  float m0 = -1e30f, m1 = -1e30f;
  float o[9][4];   // o[8] column 64 = running row-sum l
#pragma unroll
  for (int nt = 0; nt < 9; nt++)
#pragma unroll
    for (int c = 0; c < 4; c++) o[nt][c] = 0.0f;

  prefetch(0, 0);

  for (int st = 0; st < NS; st++) {
    const int buf = st & 1;
    asm volatile("cp.async.wait_group 0;\n");
    __syncthreads();  // stage st data + (all warps done with buf^1)
    if (st + 1 < NS) prefetch(st + 1, buf ^ 1);

    const bool bound = (st == NS - 1);

#pragma unroll
    for (int half = 0; half < 2; half++) {
      const __half* Ks_ = Ksb + buf * KBUF_H + (half * 64) * KS_H;
      const __half* Vt_ = Vtb + buf * VBUF_H;
      const int* mk = msk + buf * 128 + half * 64;
      const int kofs = half * 64;  // key offset within stage

      // ---- S = Q @ K^T (pre-scaled by log2e/8) ----
      float s[8][4];
#pragma unroll
      for (int nt = 0; nt < 8; nt++)
#pragma unroll
        for (int c = 0; c < 4; c++) s[nt][c] = 0.0f;

#pragma unroll
      for (int ks = 0; ks < 4; ks++) {
        const int off = ks * 16 + 4 * tig;
#pragma unroll
        for (int nt = 0; nt < 8; nt++) {
          uint2 bv = *(const uint2*)(Ks_ + (nt * 8 + g) * KS_H + off);
          uint32_t bf[2] = {bv.x, bv.y};
          mma_f16(s[nt], qf[ks], bf);
        }
      }

      // ---- mask ----
      if (bound) {
        const int k0g = (st << 7) + kofs;
#pragma unroll
        for (int nt = 0; nt < 8; nt++) {
          const int cg = k0g + nt * 8 + 2 * tig;
          const int m_a = mk[nt * 8 + 2 * tig], m_b = mk[nt * 8 + 2 * tig + 1];
          if (!(m_a && cg <= rg0)) s[nt][0] = -1e30f;
          if (!(m_b && cg + 1 <= rg0)) s[nt][1] = -1e30f;
          if (!(m_a && cg <= rg0 + 8)) s[nt][2] = -1e30f;
          if (!(m_b && cg + 1 <= rg0 + 8)) s[nt][3] = -1e30f;
        }
      } else {
#pragma unroll
        for (int nt = 0; nt < 8; nt++) {
          const int m_a = mk[nt * 8 + 2 * tig], m_b = mk[nt * 8 + 2 * tig + 1];
          if (!m_a) { s[nt][0] = -1e30f; s[nt][2] = -1e30f; }
          if (!m_b) { s[nt][1] = -1e30f; s[nt][3] = -1e30f; }
        }
      }

      // ---- online softmax (base-2): max, corr ----
      float mx0 = -1e30f, mx1 = -1e30f;
#pragma unroll
      for (int nt = 0; nt < 8; nt++) {
        mx0 = fmaxf(mx0, fmaxf(s[nt][0], s[nt][1]));
        mx1 = fmaxf(mx1, fmaxf(s[nt][2], s[nt][3]));
      }
      mx0 = fmaxf(mx0, __shfl_xor_sync(0xffffffffu, mx0, 1));
      mx0 = fmaxf(mx0, __shfl_xor_sync(0xffffffffu, mx0, 2));
      mx1 = fmaxf(mx1, __shfl_xor_sync(0xffffffffu, mx1, 1));
      mx1 = fmaxf(mx1, __shfl_xor_sync(0xffffffffu, mx1, 2));
      const float nm0 = fmaxf(m0, mx0), nm1 = fmaxf(m1, mx1);
      const float corr0 = ex2f(m0 - nm0), corr1 = ex2f(m1 - nm1);
      m0 = nm0;
      m1 = nm1;

#pragma unroll
      for (int nt = 0; nt < 9; nt++) {
        o[nt][0] *= corr0;
        o[nt][1] *= corr0;
        o[nt][2] *= corr1;
        o[nt][3] *= corr1;
      }

      // ---- P = 2^(s-nm) packed in registers: C-frag IS the PV A-frag ----
      uint32_t p0[8], p1[8];
#pragma unroll
      for (int nt = 0; nt < 8; nt++) {
        __half2 d01 = __floats2half2_rn(s[nt][0] - nm0, s[nt][1] - nm0);
        __half2 d23 = __floats2half2_rn(s[nt][2] - nm1, s[nt][3] - nm1);
        p0[nt] = h2ex2(*(uint32_t*)&d01);
        p1[nt] = h2ex2(*(uint32_t*)&d23);
      }

      // ---- O += P @ [V | ones] (nt=8 column accumulates row-sum l) ----
#pragma unroll
      for (int ks = 0; ks < 4; ks++) {
        const int off = kofs + ks * 16 + 2 * tig;
        uint32_t a[4] = {p0[2 * ks], p1[2 * ks], p0[2 * ks + 1],
                         p1[2 * ks + 1]};
#pragma unroll
        for (int nt = 0; nt < 9; nt++) {
          const __half* vb = Vt_ + (nt * 8 + g) * VT_H + off;
          uint32_t bf[2];
          bf[0] = *(const uint32_t*)(vb);
          bf[1] = *(const uint32_t*)(vb + 8);
          mma_f16(o[nt], a, bf);
        }
      }
    }
  }

  // ---- l lives in o[8] col 64 (tig=0 of each quad); broadcast ----
  const float l0 = __shfl_sync(0xffffffffu, o[8][0], lane & ~3);
  const float l1 = __shfl_sync(0xffffffffu, o[8][2], lane & ~3);
  const float inv0 = 1.0f / l0, inv1 = 1.0f / l1;

  // ---- write O fp16 perm16 to [B, L, H*Dh] for the proj GEMM ----
#pragma unroll
  for (int nt = 0; nt < 8; nt++) {
    const int dl = nt * 8 + 2 * tig;
    const int j = (dl & 15) >> 1;
    const int col = h * HDIM + (dl & ~15) + (((j & 3) * 2 + (j >> 2)) << 1);
    *(__half2*)(O + (size_t)(b * SEQ + rg0) * EMBD + col) =
        __floats2half2_rn(o[nt][0] * inv0, o[nt][1] * inv0);
    *(__half2*)(O + (size_t)(b * SEQ + rg0 + 8) * EMBD + col) =
        __floats2half2_rn(o[nt][2] * inv1, o[nt][3] * inv1);
  }
}

// ---------------------------------------------------------------------------
extern "C" void kernel_launch(void* const* d_in, const int* in_sizes, int n_in,
                              void* d_out, int out_size) {
  const float* x     = (const float*)d_in[0];
  const float* Wqkv  = (const float*)d_in[1];
  const float* bqkv  = (const float*)d_in[2];
  const float* Wproj = (const float*)d_in[3];
  const float* bproj = (const float*)d_in[4];
  const int*   amask = (const int*)d_in[5];
  float* out = (float*)d_out;

  __half *q, *k, *v, *att, *xh, *wqkvT, *wprojT;
  cudaGetSymbolAddress((void**)&q, g_q);
  cudaGetSymbolAddress((void**)&k, g_k);
  cudaGetSymbolAddress((void**)&v, g_v);
  cudaGetSymbolAddress((void**)&att, g_att);
  cudaGetSymbolAddress((void**)&xh, g_xh);
  cudaGetSymbolAddress((void**)&wqkvT, g_wqkvT);
  cudaGetSymbolAddress((void**)&wprojT, g_wprojT);

  cudaFuncSetAttribute(gemm_f16_kernel,
                       cudaFuncAttributeMaxDynamicSharedMemorySize, GEMM_SMEM);
  cudaFuncSetAttribute(gemm_qkv_rope_kernel,
                       cudaFuncAttributeMaxDynamicSharedMemorySize, GEMM_SMEM);
  cudaFuncSetAttribute(flash_mma_kernel,
                       cudaFuncAttributeMaxDynamicSharedMemorySize, FLASH_SMEM);

  // 0. Operand prep (x round+perm16 + rope table; both weight transposes)
  round_permute_rope<<<1184, 256>>>(x, xh, TOKENS * EMBD / 16);
  {
    dim3 gt(96 + 32, EMBD / 32);
    transpose_both_kernel<<<gt, dim3(32, 8)>>>(Wqkv, wqkvT, Wproj, wprojT);
  }

  // 1. QKV projection + fused RoPE/split -> q (*log2e/8), k, v
  dim3 g1(QKVDIM / 128, TOKENS / 128);
  gemm_qkv_rope_kernel<<<g1, 256, GEMM_SMEM>>>(xh, wqkvT, bqkv, q, k, v);

  // 2. Causal flash attention (fp16 tensor cores) -> att (fp16, perm16)
  dim3 g3(SEQ / 128, NHEAD, BATCH);
  flash_mma_kernel<<<g3, 256, FLASH_SMEM>>>(q, k, v, amask, att);

  // 3. Output projection -> fp32 out
  dim3 g4(EMBD / 128, TOKENS / 128);
  gemm_f16_kernel<<<g4, 256, GEMM_SMEM>>>(att, wprojT, bproj, out, EMBD, EMBD);
}